// round 4
// baseline (speedup 1.0000x reference)
#include <cuda_runtime.h>
#include <math.h>

// ---------------------------------------------------------------------------
// SRU (Simple Recurrent Unit), 2 layers.
//   layer0: proj4(xt[T,B,1024]) -> scan -> h1[T,B,512]
//   convert: h1 @ W_xl^T + b_xl -> hconv[T,B,1024]
//   layer1: proj4(hconv) -> scan -> h (d_out[0:T*B*512]), c_last (d_out[T*B*512:])
// Sigmoid of f/r gates fused into GEMM epilogue.
// ---------------------------------------------------------------------------

#define T_STEPS 512
#define BATCH   32
#define NIN     1024
#define NOUT    512
#define M_TOT   (T_STEPS * BATCH)      // 16384 rows for all GEMMs
#define E_TOT   (BATCH * NOUT)         // 16384 scan lanes

// Scratch (device globals: allocation-free per harness rules)
__device__ float g_proj[4][M_TOT * NOUT];   // x, f, r, cx projections
__device__ float g_h1[M_TOT * NOUT];        // layer0 output
__device__ float g_hconv[M_TOT * NIN];      // converted input for layer1

// ---------------------------------------------------------------------------
// GEMM (NT): Y[m,n] = act( sum_k X[m,k] * W[n,k] + bias[n] )
//   X: [M, K] row-major, W: [N, K] row-major (weights are stored K-major).
//   BM=128, BN=64, BK=16. 256 threads; per-thread 8(M) x 4(N) tile.
//   Accumulators are packed f32x2 pairs along M (fma.rn.f32x2: 2 FMAs/instr).
//   act: 0 = identity, 1 = sigmoid.
// ---------------------------------------------------------------------------
__global__ __launch_bounds__(256, 2)
void gemm_nt_kernel(const float* __restrict__ X, const float* __restrict__ W,
                    const float* __restrict__ bias, float* __restrict__ Y,
                    int K, int N, int act)
{
    __shared__ float As[16][132];   // [k][m], padded (132*4B = 16B-aligned rows)
    __shared__ float Bs[16][68];    // [k][n], padded

    const int tid = threadIdx.x;
    const int tx = tid & 15;        // n sub-tile
    const int ty = tid >> 4;        // m sub-tile
    const int m0 = ty * 8;
    const int n0 = tx * 4;
    const int mb = blockIdx.y * 128;
    const int nb = blockIdx.x * 64;

    // A loader: each thread loads 2 float4 (8 floats) from one row.
    const int a_row = tid >> 1;          // 0..127
    const int a_kq  = (tid & 1) * 2;     // float4 index 0 or 2 (covers kq, kq+1)
    // B loader: each thread loads 1 float4.
    const int b_row = tid >> 2;          // 0..63
    const int b_kq  = tid & 3;

    const float* Xrow = X + (size_t)(mb + a_row) * K + a_kq * 4;
    const float* Wrow = W + (size_t)(nb + b_row) * K + b_kq * 4;

    unsigned long long acc[4][4];
    #pragma unroll
    for (int i = 0; i < 4; i++)
        #pragma unroll
        for (int j = 0; j < 4; j++)
            acc[i][j] = 0ull;   // packed (0.0f, 0.0f)

    for (int kt = 0; kt < K; kt += 16) {
        float4 av0 = *(const float4*)(Xrow + kt);
        float4 av1 = *(const float4*)(Xrow + kt + 4);
        float4 bv  = *(const float4*)(Wrow + kt);

        __syncthreads();   // previous tile fully consumed before overwrite
        As[a_kq * 4 + 0][a_row] = av0.x;
        As[a_kq * 4 + 1][a_row] = av0.y;
        As[a_kq * 4 + 2][a_row] = av0.z;
        As[a_kq * 4 + 3][a_row] = av0.w;
        As[a_kq * 4 + 4][a_row] = av1.x;
        As[a_kq * 4 + 5][a_row] = av1.y;
        As[a_kq * 4 + 6][a_row] = av1.z;
        As[a_kq * 4 + 7][a_row] = av1.w;
        Bs[b_kq * 4 + 0][b_row] = bv.x;
        Bs[b_kq * 4 + 1][b_row] = bv.y;
        Bs[b_kq * 4 + 2][b_row] = bv.z;
        Bs[b_kq * 4 + 3][b_row] = bv.w;
        __syncthreads();

        #pragma unroll
        for (int kk = 0; kk < 16; kk++) {
            // A fragment: 8 consecutive M values = 4 packed f32x2 pairs
            ulonglong2 a01 = *(const ulonglong2*)&As[kk][m0];
            ulonglong2 a23 = *(const ulonglong2*)&As[kk][m0 + 4];
            unsigned long long ap[4] = { a01.x, a01.y, a23.x, a23.y };
            float4 b = *(const float4*)&Bs[kk][n0];
            unsigned long long bp[4];
            asm("mov.b64 %0, {%1, %1};" : "=l"(bp[0]) : "f"(b.x));
            asm("mov.b64 %0, {%1, %1};" : "=l"(bp[1]) : "f"(b.y));
            asm("mov.b64 %0, {%1, %1};" : "=l"(bp[2]) : "f"(b.z));
            asm("mov.b64 %0, {%1, %1};" : "=l"(bp[3]) : "f"(b.w));
            #pragma unroll
            for (int i = 0; i < 4; i++)
                #pragma unroll
                for (int j = 0; j < 4; j++)
                    asm("fma.rn.f32x2 %0, %1, %2, %0;"
                        : "+l"(acc[i][j]) : "l"(ap[i]), "l"(bp[j]));
        }
    }

    // Epilogue: unpack, + bias, activation, vectorized store.
    float b4x = 0.f, b4y = 0.f, b4z = 0.f, b4w = 0.f;
    if (bias) {
        float4 bv = *(const float4*)&bias[nb + n0];
        b4x = bv.x; b4y = bv.y; b4z = bv.z; b4w = bv.w;
    }
    #pragma unroll
    for (int i = 0; i < 4; i++) {
        float lo[4], hi[4];
        #pragma unroll
        for (int j = 0; j < 4; j++)
            asm("mov.b64 {%0, %1}, %2;" : "=f"(lo[j]), "=f"(hi[j]) : "l"(acc[i][j]));
        const int row = mb + m0 + 2 * i;
        float4 v0, v1;
        v0.x = lo[0] + b4x; v0.y = lo[1] + b4y; v0.z = lo[2] + b4z; v0.w = lo[3] + b4w;
        v1.x = hi[0] + b4x; v1.y = hi[1] + b4y; v1.z = hi[2] + b4z; v1.w = hi[3] + b4w;
        if (act == 1) {
            v0.x = 1.f / (1.f + __expf(-v0.x));
            v0.y = 1.f / (1.f + __expf(-v0.y));
            v0.z = 1.f / (1.f + __expf(-v0.z));
            v0.w = 1.f / (1.f + __expf(-v0.w));
            v1.x = 1.f / (1.f + __expf(-v1.x));
            v1.y = 1.f / (1.f + __expf(-v1.y));
            v1.z = 1.f / (1.f + __expf(-v1.z));
            v1.w = 1.f / (1.f + __expf(-v1.w));
        }
        *(float4*)(Y + (size_t)row * N + nb + n0)       = v0;
        *(float4*)(Y + (size_t)(row + 1) * N + nb + n0) = v1;
    }
}

// ---------------------------------------------------------------------------
// Sequential scan: one thread per (b, o) lane, T=512 steps.
//   c = f*c + (1-f)*x ;  h = r*tanh(c) + (1-r)*cx
// f, r already sigmoided in the GEMM epilogue.
// ---------------------------------------------------------------------------
__global__ __launch_bounds__(256)
void sru_scan_kernel(const float* __restrict__ px, const float* __restrict__ pf,
                     const float* __restrict__ pr, const float* __restrict__ pcx,
                     const float* __restrict__ c0, float* __restrict__ hout,
                     float* __restrict__ cout)
{
    const int e = blockIdx.x * blockDim.x + threadIdx.x;  // 0..E_TOT-1
    float c = c0[e];
    int idx = e;
    #pragma unroll 4
    for (int t = 0; t < T_STEPS; t++, idx += E_TOT) {
        float x  = px[idx];
        float f  = pf[idx];
        float r  = pr[idx];
        float cx = pcx[idx];
        c = fmaf(f, c - x, x);            // f*c + (1-f)*x
        float th = tanhf(c);
        hout[idx] = fmaf(r, th - cx, cx); // r*tanh(c) + (1-r)*cx
    }
    if (cout) cout[e] = c;
}

// ---------------------------------------------------------------------------
extern "C" void kernel_launch(void* const* d_in, const int* in_sizes, int n_in,
                              void* d_out, int out_size)
{
    (void)in_sizes; (void)n_in; (void)out_size;

    const float* xt   = (const float*)d_in[0];   // [T,B,1024]
    const float* ctf  = (const float*)d_in[1];   // [2,B,512]
    const float* W_x  = (const float*)d_in[2];   // [512,1024]
    const float* W_f  = (const float*)d_in[3];
    const float* b_f  = (const float*)d_in[4];
    const float* W_r  = (const float*)d_in[5];
    const float* b_r  = (const float*)d_in[6];
    const float* W_cx = (const float*)d_in[7];
    const float* b_cx = (const float*)d_in[8];
    const float* W_xl = (const float*)d_in[9];   // [1024,512]
    const float* b_xl = (const float*)d_in[10];
    float* out = (float*)d_out;                  // h [T,B,512] then ct [B,512]

    float *proj, *h1, *hconv;
    cudaGetSymbolAddress((void**)&proj,  g_proj);
    cudaGetSymbolAddress((void**)&h1,    g_h1);
    cudaGetSymbolAddress((void**)&hconv, g_hconv);
    float* px  = proj + 0 * (size_t)M_TOT * NOUT;
    float* pf  = proj + 1 * (size_t)M_TOT * NOUT;
    float* pr  = proj + 2 * (size_t)M_TOT * NOUT;
    float* pcx = proj + 3 * (size_t)M_TOT * NOUT;

    const dim3 blk(256);
    const dim3 grid_proj(NOUT / 64, M_TOT / 128);   // (8, 128)
    const dim3 grid_conv(NIN / 64,  M_TOT / 128);   // (16, 128)
    const dim3 grid_scan(E_TOT / 256);              // 64

    // ---- layer 0: 4 projections from xt (K = 1024) ----
    gemm_nt_kernel<<<grid_proj, blk>>>(xt, W_x,  nullptr, px,  NIN, NOUT, 0);
    gemm_nt_kernel<<<grid_proj, blk>>>(xt, W_f,  b_f,     pf,  NIN, NOUT, 1);
    gemm_nt_kernel<<<grid_proj, blk>>>(xt, W_r,  b_r,     pr,  NIN, NOUT, 1);
    gemm_nt_kernel<<<grid_proj, blk>>>(xt, W_cx, b_cx,    pcx, NIN, NOUT, 0);

    // ---- layer 0 scan -> h1 ----
    sru_scan_kernel<<<grid_scan, blk>>>(px, pf, pr, pcx, ctf, h1, nullptr);

    // ---- convert_x_layer: hconv = h1 @ W_xl^T + b_xl (K = 512, N = 1024) ----
    gemm_nt_kernel<<<grid_conv, blk>>>(h1, W_xl, b_xl, hconv, NOUT, NIN, 0);

    // ---- layer 1: 4 projections from hconv (K = 1024) ----
    gemm_nt_kernel<<<grid_proj, blk>>>(hconv, W_x,  nullptr, px,  NIN, NOUT, 0);
    gemm_nt_kernel<<<grid_proj, blk>>>(hconv, W_f,  b_f,     pf,  NIN, NOUT, 1);
    gemm_nt_kernel<<<grid_proj, blk>>>(hconv, W_r,  b_r,     pr,  NIN, NOUT, 1);
    gemm_nt_kernel<<<grid_proj, blk>>>(hconv, W_cx, b_cx,    pcx, NIN, NOUT, 0);

    // ---- layer 1 scan -> d_out (h), c_last -> d_out + T*B*512 ----
    sru_scan_kernel<<<grid_scan, blk>>>(px, pf, pr, pcx, ctf + E_TOT,
                                        out, out + (size_t)M_TOT * NOUT);
}

// round 6
// speedup vs baseline: 1.7496x; 1.7496x over previous
#include <cuda_runtime.h>
#include <cuda_fp16.h>
#include <math.h>
#include <stdint.h>

// ---------------------------------------------------------------------------
// SRU, 2 layers. Tensor cores via legacy mma.sync (HMMA) — the harness builds
// for base sm_103 (no 'a'), so tcgen05 is unavailable. Split-fp16 3-term GEMM:
//   Y = Ahi*Bhi + Ahi*Blo + Alo*Bhi   (error ~2^-22, rel_err ~1e-6)
// GEMM1/3: Y[16384,2048] = X * Wpack^T (+bias, sigmoid cols [512,1536))
// GEMM2  : hconv[16384,1024] = h1 * W_xl^T + b_xl (emitted as fp16 hi/lo)
// ---------------------------------------------------------------------------

#define T_STEPS 512
#define BATCH   32
#define NIN     1024
#define NOUT    512
#define M_TOT   16384
#define NBIG    2048
#define E_TOT   16384

// ---- scratch (device globals; allocation-free) ----
__device__ __align__(256) float  g_Y[(size_t)M_TOT * NBIG];
__device__ __align__(256) __half g_xhi[(size_t)M_TOT * NIN];
__device__ __align__(256) __half g_xlo[(size_t)M_TOT * NIN];
__device__ __align__(256) __half g_h1hi[(size_t)M_TOT * NOUT];
__device__ __align__(256) __half g_h1lo[(size_t)M_TOT * NOUT];
__device__ __align__(256) __half g_hchi[(size_t)M_TOT * NIN];
__device__ __align__(256) __half g_hclo[(size_t)M_TOT * NIN];
__device__ __align__(256) __half g_whi[(size_t)NBIG * NIN];
__device__ __align__(256) __half g_wlo[(size_t)NBIG * NIN];
__device__ __align__(256) __half g_wxlhi[(size_t)NIN * NOUT];
__device__ __align__(256) __half g_wxllo[(size_t)NIN * NOUT];
__device__ __align__(256) float  g_bias[NBIG];

// ---------------------------------------------------------------------------
// PTX helpers (all sm_80+ features; compile on base sm_103)
// ---------------------------------------------------------------------------
__device__ __forceinline__ uint32_t smem_u32(const void* p) {
    uint32_t a;
    asm("{ .reg .u64 t; cvta.to.shared.u64 t, %1; cvt.u32.u64 %0, t; }"
        : "=r"(a) : "l"(p));
    return a;
}
__device__ __forceinline__ void cp16(uint32_t d, const void* s) {
    asm volatile("cp.async.cg.shared.global [%0], [%1], 16;"
                 :: "r"(d), "l"(s) : "memory");
}
__device__ __forceinline__ void cp_commit() {
    asm volatile("cp.async.commit_group;" ::: "memory");
}
__device__ __forceinline__ void cp_wait1() {
    asm volatile("cp.async.wait_group 1;" ::: "memory");
}
__device__ __forceinline__ void ldsm4(uint32_t* r, uint32_t a) {
    asm volatile("ldmatrix.sync.aligned.m8n8.x4.shared.b16 {%0,%1,%2,%3}, [%4];"
                 : "=r"(r[0]), "=r"(r[1]), "=r"(r[2]), "=r"(r[3]) : "r"(a));
}
__device__ __forceinline__ void mma16816(float* c, const uint32_t* a,
                                         const uint32_t* b) {
    asm volatile(
        "mma.sync.aligned.m16n8k16.row.col.f32.f16.f16.f32 "
        "{%0,%1,%2,%3}, {%4,%5,%6,%7}, {%8,%9}, {%0,%1,%2,%3};"
        : "+f"(c[0]), "+f"(c[1]), "+f"(c[2]), "+f"(c[3])
        : "r"(a[0]), "r"(a[1]), "r"(a[2]), "r"(a[3]), "r"(b[0]), "r"(b[1]));
}

// ---------------------------------------------------------------------------
// GEMM: Y[M,N] = A[M,K]*B[N,K]^T over 3 segments {(Ahi,Bhi),(Ahi,Blo),(Alo,Bhi)}
// BM=128 BN=128 BK=32, 256 threads (8 warps 2x4, warp tile 64x32), 3-stage
// cp.async pipeline. Smem rows padded to 80B for conflict-free ldmatrix.
// MODE 0: fp32 out + g_bias + sigmoid on n in [512,1536)
// MODE 1: fp16 hi/lo out + fp32 bias vector
// ---------------------------------------------------------------------------
#define ROWB        80
#define STAGE_HALF  (128 * ROWB)          // 10240 B (A or B tile)
#define STAGE_BYTES (2 * STAGE_HALF)      // 20480 B
#define GEMM_SMEM   (3 * STAGE_BYTES)     // 61440 B

template <int MODE>
__global__ __launch_bounds__(256)
void gemm_tc(const __half* __restrict__ Ahi, const __half* __restrict__ Alo,
             const __half* __restrict__ Bhi, const __half* __restrict__ Blo,
             const float* __restrict__ bias,
             float* __restrict__ Yf,
             __half* __restrict__ Yhi, __half* __restrict__ Ylo,
             int K, int ldy)
{
    extern __shared__ __align__(128) char smem_dyn[];
    const uint32_t sb0 = smem_u32(smem_dyn);

    const int tid  = threadIdx.x;
    const int lane = tid & 31;
    const int wid  = tid >> 5;
    const int wm   = wid >> 2;          // 0..1
    const int wn   = wid & 3;           // 0..3
    const int m_warp = wm * 64;
    const int n_warp = wn * 32;
    const int mb = blockIdx.y * 128;
    const int nb = blockIdx.x * 128;

    const __half* Aseg[3] = { Ahi, Ahi, Alo };
    const __half* Bseg[3] = { Bhi, Blo, Bhi };

    // per-thread load mapping: 2 chunks of 16B for A and for B per stage
    const int ci0 = tid * 2;
    const int ld_row0 = ci0 >> 2,       ld_c0 = ci0 & 3;
    const int ld_row1 = (ci0 + 1) >> 2, ld_c1 = (ci0 + 1) & 3;

    // ldmatrix lane-derived offsets
    const int a_row  = m_warp + (lane & 7) + ((lane >> 3) & 1) * 8;
    const int a_coff = (lane >> 4) * 16;                 // bytes
    const int b_t    = lane >> 3;
    const int b_row  = n_warp + (b_t >> 1) * 8 + (lane & 7);
    const int b_coff = (b_t & 1) * 16;                   // bytes

    float acc[4][4][4];
    #pragma unroll
    for (int i = 0; i < 4; i++)
        #pragma unroll
        for (int j = 0; j < 4; j++)
            #pragma unroll
            for (int q = 0; q < 4; q++) acc[i][j][q] = 0.f;

    const int kPerSeg = K >> 5;
    const int nst = 3 * kPerSeg;

    // rolling issue state
    int isg = 0, ik = 0;

    auto issue = [&](int buf) {
        const __half* Ag = Aseg[isg] + (size_t)mb * K + ik;
        const __half* Bg = Bseg[isg] + (size_t)nb * K + ik;
        const uint32_t sa = sb0 + buf * STAGE_BYTES;
        const uint32_t sbB = sa + STAGE_HALF;
        cp16(sa  + ld_row0 * ROWB + ld_c0 * 16, Ag + (size_t)ld_row0 * K + ld_c0 * 8);
        cp16(sa  + ld_row1 * ROWB + ld_c1 * 16, Ag + (size_t)ld_row1 * K + ld_c1 * 8);
        cp16(sbB + ld_row0 * ROWB + ld_c0 * 16, Bg + (size_t)ld_row0 * K + ld_c0 * 8);
        cp16(sbB + ld_row1 * ROWB + ld_c1 * 16, Bg + (size_t)ld_row1 * K + ld_c1 * 8);
        ik += 32; if (ik == K) { ik = 0; isg++; }
    };

    issue(0); cp_commit();
    issue(1); cp_commit();

    for (int s = 0; s < nst; s++) {
        cp_wait1();
        __syncthreads();
        if (s + 2 < nst) issue((s + 2) % 3);
        cp_commit();

        const uint32_t sa  = sb0 + (s % 3) * STAGE_BYTES;
        const uint32_t sbB = sa + STAGE_HALF;
        #pragma unroll
        for (int kk = 0; kk < 2; kk++) {
            uint32_t a[4][4], b[2][4];
            #pragma unroll
            for (int ma = 0; ma < 4; ma++)
                ldsm4(a[ma], sa + (uint32_t)(a_row + ma * 16) * ROWB
                             + kk * 32 + a_coff);
            #pragma unroll
            for (int n2 = 0; n2 < 2; n2++)
                ldsm4(b[n2], sbB + (uint32_t)(b_row + n2 * 16) * ROWB
                             + kk * 32 + b_coff);
            #pragma unroll
            for (int ma = 0; ma < 4; ma++)
                #pragma unroll
                for (int na = 0; na < 4; na++)
                    mma16816(acc[ma][na], a[ma], &b[na >> 1][(na & 1) * 2]);
        }
        __syncthreads();
    }

    // ---- epilogue ----
    const int g  = lane >> 2;        // 0..7
    const int tg = lane & 3;         // 0..3
    #pragma unroll
    for (int ma = 0; ma < 4; ma++) {
        #pragma unroll
        for (int na = 0; na < 4; na++) {
            const int m = mb + m_warp + ma * 16 + g;
            const int n = nb + n_warp + na * 8 + tg * 2;
            const float2 bv = *(const float2*)&bias[n];
            float y0 = acc[ma][na][0] + bv.x;
            float y1 = acc[ma][na][1] + bv.y;
            float y2 = acc[ma][na][2] + bv.x;
            float y3 = acc[ma][na][3] + bv.y;
            if (MODE == 0) {
                if (n >= 512 && n < 1536) {
                    y0 = 1.f / (1.f + __expf(-y0));
                    y1 = 1.f / (1.f + __expf(-y1));
                    y2 = 1.f / (1.f + __expf(-y2));
                    y3 = 1.f / (1.f + __expf(-y3));
                }
                *(float2*)&Yf[(size_t)m * ldy + n]       = make_float2(y0, y1);
                *(float2*)&Yf[(size_t)(m + 8) * ldy + n] = make_float2(y2, y3);
            } else {
                __half h0 = __float2half_rn(y0), h1 = __float2half_rn(y1);
                __half h2 = __float2half_rn(y2), h3 = __float2half_rn(y3);
                __half l0 = __float2half_rn(y0 - __half2float(h0));
                __half l1 = __float2half_rn(y1 - __half2float(h1));
                __half l2 = __float2half_rn(y2 - __half2float(h2));
                __half l3 = __float2half_rn(y3 - __half2float(h3));
                *(__half2*)&Yhi[(size_t)m * ldy + n]       = __halves2half2(h0, h1);
                *(__half2*)&Yhi[(size_t)(m + 8) * ldy + n] = __halves2half2(h2, h3);
                *(__half2*)&Ylo[(size_t)m * ldy + n]       = __halves2half2(l0, l1);
                *(__half2*)&Ylo[(size_t)(m + 8) * ldy + n] = __halves2half2(l2, l3);
            }
        }
    }
}

// ---------------------------------------------------------------------------
// Scan: one thread per (b,o) lane. Y layout [M,2048] = x|f|r|cx, f/r sigmoided.
// SPLIT=1: emit h as fp16 hi/lo. SPLIT=0: fp32 h + c_last.
// ---------------------------------------------------------------------------
template <int SPLIT>
__global__ __launch_bounds__(128)
void sru_scan(const float* __restrict__ Y, const float* __restrict__ c0,
              float* __restrict__ hf,
              __half* __restrict__ hhi, __half* __restrict__ hlo,
              float* __restrict__ cout)
{
    const int e = blockIdx.x * 128 + threadIdx.x;
    const int b = e >> 9, o = e & 511;
    float c = c0[e];
    #pragma unroll 2
    for (int t = 0; t < T_STEPS; t++) {
        const int m = t * BATCH + b;
        const size_t base = (size_t)m * NBIG;
        float x  = Y[base + o];
        float f  = Y[base + 512 + o];
        float r  = Y[base + 1024 + o];
        float cx = Y[base + 1536 + o];
        c = fmaf(f, c - x, x);
        float h = fmaf(r, tanhf(c) - cx, cx);
        const size_t oi = (size_t)m * NOUT + o;
        if (SPLIT) {
            __half hh = __float2half_rn(h);
            hhi[oi] = hh;
            hlo[oi] = __float2half_rn(h - __half2float(hh));
        } else {
            hf[oi] = h;
        }
    }
    if (!SPLIT) cout[e] = c;
}

// ---------------------------------------------------------------------------
// fp32 -> fp16 hi/lo splits
// ---------------------------------------------------------------------------
__global__ __launch_bounds__(256)
void split_f32(const float4* __restrict__ src, uint2* __restrict__ hi,
               uint2* __restrict__ lo, int n4)
{
    const int i = blockIdx.x * 256 + threadIdx.x;
    if (i >= n4) return;
    float4 v = src[i];
    float a[4] = { v.x, v.y, v.z, v.w };
    __align__(8) __half h[4], l[4];
    #pragma unroll
    for (int j = 0; j < 4; j++) {
        h[j] = __float2half_rn(a[j]);
        l[j] = __float2half_rn(a[j] - __half2float(h[j]));
    }
    hi[i] = *(uint2*)h;
    lo[i] = *(uint2*)l;
}

__global__ __launch_bounds__(256)
void pack_w(const float* __restrict__ Wx, const float* __restrict__ Wf,
            const float* __restrict__ Wr, const float* __restrict__ Wcx,
            const float* __restrict__ bf, const float* __restrict__ br,
            const float* __restrict__ bcx)
{
    const int i = blockIdx.x * 256 + threadIdx.x;   // float4 index, 524288 total
    const int n = i * 4;
    const int row = n >> 10, col = n & 1023;
    const int sel = row >> 9, lr = row & 511;
    const float* src = sel == 0 ? Wx : sel == 1 ? Wf : sel == 2 ? Wr : Wcx;
    float4 v = *(const float4*)(src + (size_t)lr * 1024 + col);
    float a[4] = { v.x, v.y, v.z, v.w };
    __align__(8) __half h[4], l[4];
    #pragma unroll
    for (int j = 0; j < 4; j++) {
        h[j] = __float2half_rn(a[j]);
        l[j] = __float2half_rn(a[j] - __half2float(h[j]));
    }
    ((uint2*)g_whi)[i] = *(uint2*)h;
    ((uint2*)g_wlo)[i] = *(uint2*)l;

    if (i < 512) {   // bias: [0:512)=0 (x), then b_f, b_r, b_cx
        const int nb_ = i * 4;
        const int s2 = nb_ >> 9, off = nb_ & 511;
        float4 bv = make_float4(0.f, 0.f, 0.f, 0.f);
        if (s2 > 0) {
            const float* bs = s2 == 1 ? bf : s2 == 2 ? br : bcx;
            bv = *(const float4*)(bs + off);
        }
        *(float4*)(g_bias + nb_) = bv;
    }
}

__global__ __launch_bounds__(256)
void pack_wxl(const float* __restrict__ Wxl)
{
    const int i = blockIdx.x * 256 + threadIdx.x;   // 131072 float4s
    float4 v = *(const float4*)(Wxl + (size_t)i * 4);
    float a[4] = { v.x, v.y, v.z, v.w };
    __align__(8) __half h[4], l[4];
    #pragma unroll
    for (int j = 0; j < 4; j++) {
        h[j] = __float2half_rn(a[j]);
        l[j] = __float2half_rn(a[j] - __half2float(h[j]));
    }
    ((uint2*)g_wxlhi)[i] = *(uint2*)h;
    ((uint2*)g_wxllo)[i] = *(uint2*)l;
}

// ---------------------------------------------------------------------------
extern "C" void kernel_launch(void* const* d_in, const int* in_sizes, int n_in,
                              void* d_out, int out_size)
{
    (void)in_sizes; (void)n_in; (void)out_size;

    const float* xt   = (const float*)d_in[0];
    const float* ctf  = (const float*)d_in[1];
    const float* W_x  = (const float*)d_in[2];
    const float* W_f  = (const float*)d_in[3];
    const float* b_f  = (const float*)d_in[4];
    const float* W_r  = (const float*)d_in[5];
    const float* b_r  = (const float*)d_in[6];
    const float* W_cx = (const float*)d_in[7];
    const float* b_cx = (const float*)d_in[8];
    const float* W_xl = (const float*)d_in[9];
    const float* b_xl = (const float*)d_in[10];
    float* out = (float*)d_out;

    float *Y, *bias;
    __half *xhi, *xlo, *h1hi, *h1lo, *hchi, *hclo, *whi, *wlo, *wxlhi, *wxllo;
    cudaGetSymbolAddress((void**)&Y,     g_Y);
    cudaGetSymbolAddress((void**)&bias,  g_bias);
    cudaGetSymbolAddress((void**)&xhi,   g_xhi);
    cudaGetSymbolAddress((void**)&xlo,   g_xlo);
    cudaGetSymbolAddress((void**)&h1hi,  g_h1hi);
    cudaGetSymbolAddress((void**)&h1lo,  g_h1lo);
    cudaGetSymbolAddress((void**)&hchi,  g_hchi);
    cudaGetSymbolAddress((void**)&hclo,  g_hclo);
    cudaGetSymbolAddress((void**)&whi,   g_whi);
    cudaGetSymbolAddress((void**)&wlo,   g_wlo);
    cudaGetSymbolAddress((void**)&wxlhi, g_wxlhi);
    cudaGetSymbolAddress((void**)&wxllo, g_wxllo);

    cudaFuncSetAttribute(gemm_tc<0>, cudaFuncAttributeMaxDynamicSharedMemorySize,
                         GEMM_SMEM);
    cudaFuncSetAttribute(gemm_tc<1>, cudaFuncAttributeMaxDynamicSharedMemorySize,
                         GEMM_SMEM);

    // conversions
    pack_w<<<2048, 256>>>(W_x, W_f, W_r, W_cx, b_f, b_r, b_cx);
    pack_wxl<<<512, 256>>>(W_xl);
    split_f32<<<16384, 256>>>((const float4*)xt, (uint2*)xhi, (uint2*)xlo,
                              M_TOT * NIN / 4);

    // layer 0: fused 4-projection GEMM (N=2048) + scan
    gemm_tc<0><<<dim3(16, 128), 256, GEMM_SMEM>>>(xhi, xlo, whi, wlo, bias,
                                                  Y, nullptr, nullptr, NIN, NBIG);
    sru_scan<1><<<128, 128>>>(Y, ctf, nullptr, h1hi, h1lo, nullptr);

    // convert_x_layer: hconv = h1 @ W_xl^T + b_xl (fp16 hi/lo out)
    gemm_tc<1><<<dim3(8, 128), 256, GEMM_SMEM>>>(h1hi, h1lo, wxlhi, wxllo, b_xl,
                                                 nullptr, hchi, hclo, NOUT, NIN);

    // layer 1: fused 4-projection GEMM + scan
    gemm_tc<0><<<dim3(16, 128), 256, GEMM_SMEM>>>(hchi, hclo, whi, wlo, bias,
                                                  Y, nullptr, nullptr, NIN, NBIG);
    sru_scan<0><<<128, 128>>>(Y, ctf + E_TOT, out, nullptr, nullptr,
                              out + (size_t)M_TOT * NOUT);
}

// round 7
// speedup vs baseline: 1.9335x; 1.1051x over previous
#include <cuda_runtime.h>
#include <cuda_fp16.h>
#include <math.h>
#include <stdint.h>

// ---------------------------------------------------------------------------
// SRU, 2 layers. Legacy mma.sync HMMA (base sm_103 target; no tcgen05).
// Split-fp16 3-term GEMM: Y = Ahi*Bhi + Ahi*Blo + Alo*Bhi  (rel ~1e-5)
// R7: warp tile 64x64 (block 128x256), 4-stage cp.async, 1 sync/stage.
// ---------------------------------------------------------------------------

#define T_STEPS 512
#define BATCH   32
#define NIN     1024
#define NOUT    512
#define M_TOT   16384
#define NBIG    2048
#define E_TOT   16384

__device__ __align__(256) float  g_Y[(size_t)M_TOT * NBIG];
__device__ __align__(256) __half g_xhi[(size_t)M_TOT * NIN];
__device__ __align__(256) __half g_xlo[(size_t)M_TOT * NIN];
__device__ __align__(256) __half g_h1hi[(size_t)M_TOT * NOUT];
__device__ __align__(256) __half g_h1lo[(size_t)M_TOT * NOUT];
__device__ __align__(256) __half g_hchi[(size_t)M_TOT * NIN];
__device__ __align__(256) __half g_hclo[(size_t)M_TOT * NIN];
__device__ __align__(256) __half g_whi[(size_t)NBIG * NIN];
__device__ __align__(256) __half g_wlo[(size_t)NBIG * NIN];
__device__ __align__(256) __half g_wxlhi[(size_t)NIN * NOUT];
__device__ __align__(256) __half g_wxllo[(size_t)NIN * NOUT];
__device__ __align__(256) float  g_bias[NBIG];

// ---------------------------------------------------------------------------
__device__ __forceinline__ uint32_t smem_u32(const void* p) {
    uint32_t a;
    asm("{ .reg .u64 t; cvta.to.shared.u64 t, %1; cvt.u32.u64 %0, t; }"
        : "=r"(a) : "l"(p));
    return a;
}
__device__ __forceinline__ void cp16(uint32_t d, const void* s) {
    asm volatile("cp.async.cg.shared.global [%0], [%1], 16;"
                 :: "r"(d), "l"(s) : "memory");
}
__device__ __forceinline__ void cp_commit() {
    asm volatile("cp.async.commit_group;" ::: "memory");
}
__device__ __forceinline__ void cp_wait2() {
    asm volatile("cp.async.wait_group 2;" ::: "memory");
}
__device__ __forceinline__ void ldsm4(uint32_t* r, uint32_t a) {
    asm volatile("ldmatrix.sync.aligned.m8n8.x4.shared.b16 {%0,%1,%2,%3}, [%4];"
                 : "=r"(r[0]), "=r"(r[1]), "=r"(r[2]), "=r"(r[3]) : "r"(a));
}
__device__ __forceinline__ void mma16816(float* c, const uint32_t* a,
                                         const uint32_t* b) {
    asm volatile(
        "mma.sync.aligned.m16n8k16.row.col.f32.f16.f16.f32 "
        "{%0,%1,%2,%3}, {%4,%5,%6,%7}, {%8,%9}, {%0,%1,%2,%3};"
        : "+f"(c[0]), "+f"(c[1]), "+f"(c[2]), "+f"(c[3])
        : "r"(a[0]), "r"(a[1]), "r"(a[2]), "r"(a[3]), "r"(b[0]), "r"(b[1]));
}

// ---------------------------------------------------------------------------
// GEMM: Y[M,N] = A[M,K]*B[N,K]^T over 3 segments. BM=128 BN=256 BK=32,
// 256 threads (8 warps, 2(m) x 4(n)), warp tile 64x64, 4-stage cp.async.
// Smem rows 80 B (conflict-free ldmatrix). One __syncthreads per stage.
// MODE 0: fp32 out + g_bias + sigmoid on n in [512,1536)
// MODE 1: fp16 hi/lo out + fp32 bias vector
// ---------------------------------------------------------------------------
#define ROWB        80
#define A_BYTES     (128 * ROWB)          // 10240
#define B_BYTES     (256 * ROWB)          // 20480
#define STAGE_BYTES (A_BYTES + B_BYTES)   // 30720
#define GEMM_SMEM   (4 * STAGE_BYTES)     // 122880

template <int MODE>
__global__ __launch_bounds__(256, 1)
void gemm_tc(const __half* __restrict__ Ahi, const __half* __restrict__ Alo,
             const __half* __restrict__ Bhi, const __half* __restrict__ Blo,
             const float* __restrict__ bias,
             float* __restrict__ Yf,
             __half* __restrict__ Yhi, __half* __restrict__ Ylo,
             int K, int ldy)
{
    extern __shared__ __align__(128) char smem_dyn[];
    const uint32_t sb0 = smem_u32(smem_dyn);

    const int tid  = threadIdx.x;
    const int lane = tid & 31;
    const int wid  = tid >> 5;
    const int m_warp = (wid >> 2) * 64;    // 0,64
    const int n_warp = (wid & 3) * 64;     // 0,64,128,192
    const int mb = blockIdx.y * 128;
    const int nb = blockIdx.x * 256;

    const __half* Aseg[3] = { Ahi, Ahi, Alo };
    const __half* Bseg[3] = { Bhi, Blo, Bhi };

    // ldmatrix lane addressing
    const int a_row  = m_warp + (lane & 15);
    const int a_coff = (lane >> 4) * 16;            // bytes within k16 slab
    const int b_t    = lane >> 3;
    const int b_row  = n_warp + (b_t >> 1) * 8 + (lane & 7);
    const int b_coff = (b_t & 1) * 16;

    float acc[4][8][4];
    #pragma unroll
    for (int i = 0; i < 4; i++)
        #pragma unroll
        for (int j = 0; j < 8; j++)
            #pragma unroll
            for (int q = 0; q < 4; q++) acc[i][j][q] = 0.f;

    const int nst = 3 * (K >> 5);
    int isg = 0, ik = 0;

    auto issue = [&](int buf) {
        const __half* Ag = Aseg[isg] + (size_t)mb * K + ik;
        const __half* Bg = Bseg[isg] + (size_t)nb * K + ik;
        const uint32_t sa  = sb0 + buf * STAGE_BYTES;
        const uint32_t sbB = sa + A_BYTES;
        #pragma unroll
        for (int i = 0; i < 2; i++) {           // A: 512 16B chunks
            const int c = tid + i * 256;
            const int r = c >> 2, cc = c & 3;
            cp16(sa + r * ROWB + cc * 16, Ag + (size_t)r * K + cc * 8);
        }
        #pragma unroll
        for (int i = 0; i < 4; i++) {           // B: 1024 16B chunks
            const int c = tid + i * 256;
            const int r = c >> 2, cc = c & 3;
            cp16(sbB + r * ROWB + cc * 16, Bg + (size_t)r * K + cc * 8);
        }
        ik += 32; if (ik == K) { ik = 0; isg++; }
    };

    issue(0); cp_commit();
    issue(1); cp_commit();
    issue(2); cp_commit();

    for (int s = 0; s < nst; s++) {
        cp_wait2();
        __syncthreads();
        if (s + 3 < nst) issue((s + 3) & 3);
        cp_commit();

        const uint32_t sa  = sb0 + (s & 3) * STAGE_BYTES;
        const uint32_t sbB = sa + A_BYTES;
        #pragma unroll
        for (int kk = 0; kk < 2; kk++) {
            uint32_t a[4][4], b[4][4];
            #pragma unroll
            for (int ma = 0; ma < 4; ma++)
                ldsm4(a[ma], sa + (uint32_t)(a_row + ma * 16) * ROWB
                             + kk * 32 + a_coff);
            #pragma unroll
            for (int n2 = 0; n2 < 4; n2++)
                ldsm4(b[n2], sbB + (uint32_t)(b_row + n2 * 16) * ROWB
                             + kk * 32 + b_coff);
            #pragma unroll
            for (int ma = 0; ma < 4; ma++)
                #pragma unroll
                for (int na = 0; na < 8; na++)
                    mma16816(acc[ma][na], a[ma], &b[na >> 1][(na & 1) * 2]);
        }
    }

    // ---- epilogue ----
    const int g  = lane >> 2;
    const int tg = lane & 3;
    #pragma unroll
    for (int ma = 0; ma < 4; ma++) {
        #pragma unroll
        for (int na = 0; na < 8; na++) {
            const int m = mb + m_warp + ma * 16 + g;
            const int n = nb + n_warp + na * 8 + tg * 2;
            const float2 bv = *(const float2*)&bias[n];
            float y0 = acc[ma][na][0] + bv.x;
            float y1 = acc[ma][na][1] + bv.y;
            float y2 = acc[ma][na][2] + bv.x;
            float y3 = acc[ma][na][3] + bv.y;
            if (MODE == 0) {
                if (n >= 512 && n < 1536) {
                    y0 = 1.f / (1.f + __expf(-y0));
                    y1 = 1.f / (1.f + __expf(-y1));
                    y2 = 1.f / (1.f + __expf(-y2));
                    y3 = 1.f / (1.f + __expf(-y3));
                }
                *(float2*)&Yf[(size_t)m * ldy + n]       = make_float2(y0, y1);
                *(float2*)&Yf[(size_t)(m + 8) * ldy + n] = make_float2(y2, y3);
            } else {
                __half h0 = __float2half_rn(y0), h1 = __float2half_rn(y1);
                __half h2 = __float2half_rn(y2), h3 = __float2half_rn(y3);
                __half l0 = __float2half_rn(y0 - __half2float(h0));
                __half l1 = __float2half_rn(y1 - __half2float(h1));
                __half l2 = __float2half_rn(y2 - __half2float(h2));
                __half l3 = __float2half_rn(y3 - __half2float(h3));
                *(__half2*)&Yhi[(size_t)m * ldy + n]       = __halves2half2(h0, h1);
                *(__half2*)&Yhi[(size_t)(m + 8) * ldy + n] = __halves2half2(h2, h3);
                *(__half2*)&Ylo[(size_t)m * ldy + n]       = __halves2half2(l0, l1);
                *(__half2*)&Ylo[(size_t)(m + 8) * ldy + n] = __halves2half2(l2, l3);
            }
        }
    }
}

// ---------------------------------------------------------------------------
// Scan: one thread per (b,o). Y layout [M,2048] = x|f|r|cx (f/r sigmoided).
// ---------------------------------------------------------------------------
template <int SPLIT>
__global__ __launch_bounds__(128)
void sru_scan(const float* __restrict__ Y, const float* __restrict__ c0,
              float* __restrict__ hf,
              __half* __restrict__ hhi, __half* __restrict__ hlo,
              float* __restrict__ cout)
{
    const int e = blockIdx.x * 128 + threadIdx.x;
    const int b = e >> 9, o = e & 511;
    float c = c0[e];
    #pragma unroll 2
    for (int t = 0; t < T_STEPS; t++) {
        const int m = t * BATCH + b;
        const size_t base = (size_t)m * NBIG;
        float x  = Y[base + o];
        float f  = Y[base + 512 + o];
        float r  = Y[base + 1024 + o];
        float cx = Y[base + 1536 + o];
        c = fmaf(f, c - x, x);
        float h = fmaf(r, tanhf(c) - cx, cx);
        const size_t oi = (size_t)m * NOUT + o;
        if (SPLIT) {
            __half hh = __float2half_rn(h);
            hhi[oi] = hh;
            hlo[oi] = __float2half_rn(h - __half2float(hh));
        } else {
            hf[oi] = h;
        }
    }
    if (!SPLIT) cout[e] = c;
}

// ---------------------------------------------------------------------------
__global__ __launch_bounds__(256)
void split_f32(const float4* __restrict__ src, uint2* __restrict__ hi,
               uint2* __restrict__ lo, int n4)
{
    const int i = blockIdx.x * 256 + threadIdx.x;
    if (i >= n4) return;
    float4 v = src[i];
    float a[4] = { v.x, v.y, v.z, v.w };
    __align__(8) __half h[4], l[4];
    #pragma unroll
    for (int j = 0; j < 4; j++) {
        h[j] = __float2half_rn(a[j]);
        l[j] = __float2half_rn(a[j] - __half2float(h[j]));
    }
    hi[i] = *(uint2*)h;
    lo[i] = *(uint2*)l;
}

__global__ __launch_bounds__(256)
void pack_w(const float* __restrict__ Wx, const float* __restrict__ Wf,
            const float* __restrict__ Wr, const float* __restrict__ Wcx,
            const float* __restrict__ bf, const float* __restrict__ br,
            const float* __restrict__ bcx)
{
    const int i = blockIdx.x * 256 + threadIdx.x;   // float4 idx, 524288 total
    const int n = i * 4;
    const int row = n >> 10, col = n & 1023;
    const int sel = row >> 9, lr = row & 511;
    const float* src = sel == 0 ? Wx : sel == 1 ? Wf : sel == 2 ? Wr : Wcx;
    float4 v = *(const float4*)(src + (size_t)lr * 1024 + col);
    float a[4] = { v.x, v.y, v.z, v.w };
    __align__(8) __half h[4], l[4];
    #pragma unroll
    for (int j = 0; j < 4; j++) {
        h[j] = __float2half_rn(a[j]);
        l[j] = __float2half_rn(a[j] - __half2float(h[j]));
    }
    ((uint2*)g_whi)[i] = *(uint2*)h;
    ((uint2*)g_wlo)[i] = *(uint2*)l;

    if (i < 512) {
        const int nb_ = i * 4;
        const int s2 = nb_ >> 9, off = nb_ & 511;
        float4 bv = make_float4(0.f, 0.f, 0.f, 0.f);
        if (s2 > 0) {
            const float* bs = s2 == 1 ? bf : s2 == 2 ? br : bcx;
            bv = *(const float4*)(bs + off);
        }
        *(float4*)(g_bias + nb_) = bv;
    }
}

__global__ __launch_bounds__(256)
void pack_wxl(const float* __restrict__ Wxl)
{
    const int i = blockIdx.x * 256 + threadIdx.x;   // 131072 float4s
    float4 v = *(const float4*)(Wxl + (size_t)i * 4);
    float a[4] = { v.x, v.y, v.z, v.w };
    __align__(8) __half h[4], l[4];
    #pragma unroll
    for (int j = 0; j < 4; j++) {
        h[j] = __float2half_rn(a[j]);
        l[j] = __float2half_rn(a[j] - __half2float(h[j]));
    }
    ((uint2*)g_wxlhi)[i] = *(uint2*)h;
    ((uint2*)g_wxllo)[i] = *(uint2*)l;
}

// ---------------------------------------------------------------------------
extern "C" void kernel_launch(void* const* d_in, const int* in_sizes, int n_in,
                              void* d_out, int out_size)
{
    (void)in_sizes; (void)n_in; (void)out_size;

    const float* xt   = (const float*)d_in[0];
    const float* ctf  = (const float*)d_in[1];
    const float* W_x  = (const float*)d_in[2];
    const float* W_f  = (const float*)d_in[3];
    const float* b_f  = (const float*)d_in[4];
    const float* W_r  = (const float*)d_in[5];
    const float* b_r  = (const float*)d_in[6];
    const float* W_cx = (const float*)d_in[7];
    const float* b_cx = (const float*)d_in[8];
    const float* W_xl = (const float*)d_in[9];
    const float* b_xl = (const float*)d_in[10];
    float* out = (float*)d_out;

    float *Y, *bias;
    __half *xhi, *xlo, *h1hi, *h1lo, *hchi, *hclo, *whi, *wlo, *wxlhi, *wxllo;
    cudaGetSymbolAddress((void**)&Y,     g_Y);
    cudaGetSymbolAddress((void**)&bias,  g_bias);
    cudaGetSymbolAddress((void**)&xhi,   g_xhi);
    cudaGetSymbolAddress((void**)&xlo,   g_xlo);
    cudaGetSymbolAddress((void**)&h1hi,  g_h1hi);
    cudaGetSymbolAddress((void**)&h1lo,  g_h1lo);
    cudaGetSymbolAddress((void**)&hchi,  g_hchi);
    cudaGetSymbolAddress((void**)&hclo,  g_hclo);
    cudaGetSymbolAddress((void**)&whi,   g_whi);
    cudaGetSymbolAddress((void**)&wlo,   g_wlo);
    cudaGetSymbolAddress((void**)&wxlhi, g_wxlhi);
    cudaGetSymbolAddress((void**)&wxllo, g_wxllo);

    cudaFuncSetAttribute(gemm_tc<0>, cudaFuncAttributeMaxDynamicSharedMemorySize,
                         GEMM_SMEM);
    cudaFuncSetAttribute(gemm_tc<1>, cudaFuncAttributeMaxDynamicSharedMemorySize,
                         GEMM_SMEM);

    pack_w<<<2048, 256>>>(W_x, W_f, W_r, W_cx, b_f, b_r, b_cx);
    pack_wxl<<<512, 256>>>(W_xl);
    split_f32<<<16384, 256>>>((const float4*)xt, (uint2*)xhi, (uint2*)xlo,
                              M_TOT * NIN / 4);

    // layer 0: fused 4-projection GEMM (N=2048) + scan
    gemm_tc<0><<<dim3(8, 128), 256, GEMM_SMEM>>>(xhi, xlo, whi, wlo, bias,
                                                 Y, nullptr, nullptr, NIN, NBIG);
    sru_scan<1><<<128, 128>>>(Y, ctf, nullptr, h1hi, h1lo, nullptr);

    // convert_x_layer: hconv = h1 @ W_xl^T + b_xl (fp16 hi/lo out)
    gemm_tc<1><<<dim3(4, 128), 256, GEMM_SMEM>>>(h1hi, h1lo, wxlhi, wxllo, b_xl,
                                                 nullptr, hchi, hclo, NOUT, NIN);

    // layer 1: fused 4-projection GEMM + scan
    gemm_tc<0><<<dim3(8, 128), 256, GEMM_SMEM>>>(hchi, hclo, whi, wlo, bias,
                                                 Y, nullptr, nullptr, NIN, NBIG);
    sru_scan<0><<<128, 128>>>(Y, ctf + E_TOT, out, nullptr, nullptr,
                              out + (size_t)M_TOT * NOUT);
}

// round 8
// speedup vs baseline: 2.0385x; 1.0543x over previous
#include <cuda_runtime.h>
#include <cuda_fp16.h>
#include <math.h>
#include <stdint.h>

// ---------------------------------------------------------------------------
// SRU, 2 layers. Legacy mma.sync HMMA (base sm_103 target; no tcgen05).
// Split-fp16 3-term GEMM: Y = Ahi*Bhi + Ahi*Blo + Alo*Bhi  (rel ~1e-5)
// R8: 512 threads / 16 warps (4 per SMSP) to fix tensor-pipe issue starvation.
//     Block tile 128x256, warp tile 64x32, 4-stage cp.async, 1 sync/stage.
// ---------------------------------------------------------------------------

#define T_STEPS 512
#define BATCH   32
#define NIN     1024
#define NOUT    512
#define M_TOT   16384
#define NBIG    2048
#define E_TOT   16384

__device__ __align__(256) float  g_Y[(size_t)M_TOT * NBIG];
__device__ __align__(256) __half g_xhi[(size_t)M_TOT * NIN];
__device__ __align__(256) __half g_xlo[(size_t)M_TOT * NIN];
__device__ __align__(256) __half g_h1hi[(size_t)M_TOT * NOUT];
__device__ __align__(256) __half g_h1lo[(size_t)M_TOT * NOUT];
__device__ __align__(256) __half g_hchi[(size_t)M_TOT * NIN];
__device__ __align__(256) __half g_hclo[(size_t)M_TOT * NIN];
__device__ __align__(256) __half g_whi[(size_t)NBIG * NIN];
__device__ __align__(256) __half g_wlo[(size_t)NBIG * NIN];
__device__ __align__(256) __half g_wxlhi[(size_t)NIN * NOUT];
__device__ __align__(256) __half g_wxllo[(size_t)NIN * NOUT];
__device__ __align__(256) float  g_bias[NBIG];

// ---------------------------------------------------------------------------
__device__ __forceinline__ uint32_t smem_u32(const void* p) {
    uint32_t a;
    asm("{ .reg .u64 t; cvta.to.shared.u64 t, %1; cvt.u32.u64 %0, t; }"
        : "=r"(a) : "l"(p));
    return a;
}
__device__ __forceinline__ void cp16(uint32_t d, const void* s) {
    asm volatile("cp.async.cg.shared.global [%0], [%1], 16;"
                 :: "r"(d), "l"(s) : "memory");
}
__device__ __forceinline__ void cp_commit() {
    asm volatile("cp.async.commit_group;" ::: "memory");
}
__device__ __forceinline__ void cp_wait2() {
    asm volatile("cp.async.wait_group 2;" ::: "memory");
}
__device__ __forceinline__ void ldsm4(uint32_t* r, uint32_t a) {
    asm volatile("ldmatrix.sync.aligned.m8n8.x4.shared.b16 {%0,%1,%2,%3}, [%4];"
                 : "=r"(r[0]), "=r"(r[1]), "=r"(r[2]), "=r"(r[3]) : "r"(a));
}
__device__ __forceinline__ void mma16816(float* c, const uint32_t* a,
                                         const uint32_t* b) {
    asm volatile(
        "mma.sync.aligned.m16n8k16.row.col.f32.f16.f16.f32 "
        "{%0,%1,%2,%3}, {%4,%5,%6,%7}, {%8,%9}, {%0,%1,%2,%3};"
        : "+f"(c[0]), "+f"(c[1]), "+f"(c[2]), "+f"(c[3])
        : "r"(a[0]), "r"(a[1]), "r"(a[2]), "r"(a[3]), "r"(b[0]), "r"(b[1]));
}

// ---------------------------------------------------------------------------
// GEMM: Y[M,N] = A[M,K]*B[N,K]^T over 3 segments. BM=128 BN=256 BK=32,
// 512 threads (16 warps: 2(m) x 8(n)), warp tile 64x32, 4-stage cp.async.
// Smem rows 80 B (conflict-free ldmatrix). One __syncthreads per stage.
// MODE 0: fp32 out + g_bias + sigmoid on n in [512,1536)
// MODE 1: fp16 hi/lo out + fp32 bias vector
// ---------------------------------------------------------------------------
#define ROWB        80
#define A_BYTES     (128 * ROWB)          // 10240
#define B_BYTES     (256 * ROWB)          // 20480
#define STAGE_BYTES (A_BYTES + B_BYTES)   // 30720
#define GEMM_SMEM   (4 * STAGE_BYTES)     // 122880

template <int MODE>
__global__ __launch_bounds__(512, 1)
void gemm_tc(const __half* __restrict__ Ahi, const __half* __restrict__ Alo,
             const __half* __restrict__ Bhi, const __half* __restrict__ Blo,
             const float* __restrict__ bias,
             float* __restrict__ Yf,
             __half* __restrict__ Yhi, __half* __restrict__ Ylo,
             int K, int ldy)
{
    extern __shared__ __align__(128) char smem_dyn[];
    const uint32_t sb0 = smem_u32(smem_dyn);

    const int tid  = threadIdx.x;
    const int lane = tid & 31;
    const int wid  = tid >> 5;               // 0..15
    const int m_warp = (wid >> 3) * 64;      // 0,64
    const int n_warp = (wid & 7) * 32;       // 0..224
    const int mb = blockIdx.y * 128;
    const int nb = blockIdx.x * 256;

    const __half* Aseg[3] = { Ahi, Ahi, Alo };
    const __half* Bseg[3] = { Bhi, Blo, Bhi };

    // ldmatrix lane addressing
    const int a_row  = m_warp + (lane & 15);
    const int a_coff = (lane >> 4) * 16;            // bytes within k16 slab
    const int b_t    = lane >> 3;
    const int b_row  = n_warp + (b_t >> 1) * 8 + (lane & 7);
    const int b_coff = (b_t & 1) * 16;

    float acc[4][4][4];
    #pragma unroll
    for (int i = 0; i < 4; i++)
        #pragma unroll
        for (int j = 0; j < 4; j++)
            #pragma unroll
            for (int q = 0; q < 4; q++) acc[i][j][q] = 0.f;

    const int nst = 3 * (K >> 5);
    int isg = 0, ik = 0;

    auto issue = [&](int buf) {
        const __half* Ag = Aseg[isg] + (size_t)mb * K + ik;
        const __half* Bg = Bseg[isg] + (size_t)nb * K + ik;
        const uint32_t sa  = sb0 + buf * STAGE_BYTES;
        const uint32_t sbB = sa + A_BYTES;
        {   // A: 512 16B chunks / 512 threads
            const int r = tid >> 2, cc = tid & 3;
            cp16(sa + r * ROWB + cc * 16, Ag + (size_t)r * K + cc * 8);
        }
        #pragma unroll
        for (int i = 0; i < 2; i++) {           // B: 1024 16B chunks
            const int c = tid + i * 512;
            const int r = c >> 2, cc = c & 3;
            cp16(sbB + r * ROWB + cc * 16, Bg + (size_t)r * K + cc * 8);
        }
        ik += 32; if (ik == K) { ik = 0; isg++; }
    };

    issue(0); cp_commit();
    issue(1); cp_commit();
    issue(2); cp_commit();

    for (int s = 0; s < nst; s++) {
        cp_wait2();
        __syncthreads();
        if (s + 3 < nst) issue((s + 3) & 3);
        cp_commit();

        const uint32_t sa  = sb0 + (s & 3) * STAGE_BYTES;
        const uint32_t sbB = sa + A_BYTES;
        #pragma unroll
        for (int kk = 0; kk < 2; kk++) {
            uint32_t a[4][4], b[2][4];
            #pragma unroll
            for (int ma = 0; ma < 4; ma++)
                ldsm4(a[ma], sa + (uint32_t)(a_row + ma * 16) * ROWB
                             + kk * 32 + a_coff);
            #pragma unroll
            for (int n2 = 0; n2 < 2; n2++)
                ldsm4(b[n2], sbB + (uint32_t)(b_row + n2 * 16) * ROWB
                             + kk * 32 + b_coff);
            #pragma unroll
            for (int ma = 0; ma < 4; ma++)
                #pragma unroll
                for (int na = 0; na < 4; na++)
                    mma16816(acc[ma][na], a[ma], &b[na >> 1][(na & 1) * 2]);
        }
    }

    // ---- epilogue ----
    const int g  = lane >> 2;
    const int tg = lane & 3;
    #pragma unroll
    for (int ma = 0; ma < 4; ma++) {
        #pragma unroll
        for (int na = 0; na < 4; na++) {
            const int m = mb + m_warp + ma * 16 + g;
            const int n = nb + n_warp + na * 8 + tg * 2;
            const float2 bv = *(const float2*)&bias[n];
            float y0 = acc[ma][na][0] + bv.x;
            float y1 = acc[ma][na][1] + bv.y;
            float y2 = acc[ma][na][2] + bv.x;
            float y3 = acc[ma][na][3] + bv.y;
            if (MODE == 0) {
                if (n >= 512 && n < 1536) {
                    y0 = 1.f / (1.f + __expf(-y0));
                    y1 = 1.f / (1.f + __expf(-y1));
                    y2 = 1.f / (1.f + __expf(-y2));
                    y3 = 1.f / (1.f + __expf(-y3));
                }
                *(float2*)&Yf[(size_t)m * ldy + n]       = make_float2(y0, y1);
                *(float2*)&Yf[(size_t)(m + 8) * ldy + n] = make_float2(y2, y3);
            } else {
                __half h0 = __float2half_rn(y0), h1 = __float2half_rn(y1);
                __half h2 = __float2half_rn(y2), h3 = __float2half_rn(y3);
                __half l0 = __float2half_rn(y0 - __half2float(h0));
                __half l1 = __float2half_rn(y1 - __half2float(h1));
                __half l2 = __float2half_rn(y2 - __half2float(h2));
                __half l3 = __float2half_rn(y3 - __half2float(h3));
                *(__half2*)&Yhi[(size_t)m * ldy + n]       = __halves2half2(h0, h1);
                *(__half2*)&Yhi[(size_t)(m + 8) * ldy + n] = __halves2half2(h2, h3);
                *(__half2*)&Ylo[(size_t)m * ldy + n]       = __halves2half2(l0, l1);
                *(__half2*)&Ylo[(size_t)(m + 8) * ldy + n] = __halves2half2(l2, l3);
            }
        }
    }
}

// ---------------------------------------------------------------------------
// Scan: one thread per (b,o). Y layout [M,2048] = x|f|r|cx (f/r sigmoided).
// ---------------------------------------------------------------------------
template <int SPLIT>
__global__ __launch_bounds__(128)
void sru_scan(const float* __restrict__ Y, const float* __restrict__ c0,
              float* __restrict__ hf,
              __half* __restrict__ hhi, __half* __restrict__ hlo,
              float* __restrict__ cout)
{
    const int e = blockIdx.x * 128 + threadIdx.x;
    const int b = e >> 9, o = e & 511;
    float c = c0[e];
    #pragma unroll 2
    for (int t = 0; t < T_STEPS; t++) {
        const int m = t * BATCH + b;
        const size_t base = (size_t)m * NBIG;
        float x  = Y[base + o];
        float f  = Y[base + 512 + o];
        float r  = Y[base + 1024 + o];
        float cx = Y[base + 1536 + o];
        c = fmaf(f, c - x, x);
        float h = fmaf(r, tanhf(c) - cx, cx);
        const size_t oi = (size_t)m * NOUT + o;
        if (SPLIT) {
            __half hh = __float2half_rn(h);
            hhi[oi] = hh;
            hlo[oi] = __float2half_rn(h - __half2float(hh));
        } else {
            hf[oi] = h;
        }
    }
    if (!SPLIT) cout[e] = c;
}

// ---------------------------------------------------------------------------
__global__ __launch_bounds__(256)
void split_f32(const float4* __restrict__ src, uint2* __restrict__ hi,
               uint2* __restrict__ lo, int n4)
{
    const int i = blockIdx.x * 256 + threadIdx.x;
    if (i >= n4) return;
    float4 v = src[i];
    float a[4] = { v.x, v.y, v.z, v.w };
    __align__(8) __half h[4], l[4];
    #pragma unroll
    for (int j = 0; j < 4; j++) {
        h[j] = __float2half_rn(a[j]);
        l[j] = __float2half_rn(a[j] - __half2float(h[j]));
    }
    hi[i] = *(uint2*)h;
    lo[i] = *(uint2*)l;
}

__global__ __launch_bounds__(256)
void pack_w(const float* __restrict__ Wx, const float* __restrict__ Wf,
            const float* __restrict__ Wr, const float* __restrict__ Wcx,
            const float* __restrict__ bf, const float* __restrict__ br,
            const float* __restrict__ bcx)
{
    const int i = blockIdx.x * 256 + threadIdx.x;   // float4 idx, 524288 total
    const int n = i * 4;
    const int row = n >> 10, col = n & 1023;
    const int sel = row >> 9, lr = row & 511;
    const float* src = sel == 0 ? Wx : sel == 1 ? Wf : sel == 2 ? Wr : Wcx;
    float4 v = *(const float4*)(src + (size_t)lr * 1024 + col);
    float a[4] = { v.x, v.y, v.z, v.w };
    __align__(8) __half h[4], l[4];
    #pragma unroll
    for (int j = 0; j < 4; j++) {
        h[j] = __float2half_rn(a[j]);
        l[j] = __float2half_rn(a[j] - __half2float(h[j]));
    }
    ((uint2*)g_whi)[i] = *(uint2*)h;
    ((uint2*)g_wlo)[i] = *(uint2*)l;

    if (i < 512) {
        const int nb_ = i * 4;
        const int s2 = nb_ >> 9, off = nb_ & 511;
        float4 bv = make_float4(0.f, 0.f, 0.f, 0.f);
        if (s2 > 0) {
            const float* bs = s2 == 1 ? bf : s2 == 2 ? br : bcx;
            bv = *(const float4*)(bs + off);
        }
        *(float4*)(g_bias + nb_) = bv;
    }
}

__global__ __launch_bounds__(256)
void pack_wxl(const float* __restrict__ Wxl)
{
    const int i = blockIdx.x * 256 + threadIdx.x;   // 131072 float4s
    float4 v = *(const float4*)(Wxl + (size_t)i * 4);
    float a[4] = { v.x, v.y, v.z, v.w };
    __align__(8) __half h[4], l[4];
    #pragma unroll
    for (int j = 0; j < 4; j++) {
        h[j] = __float2half_rn(a[j]);
        l[j] = __float2half_rn(a[j] - __half2float(h[j]));
    }
    ((uint2*)g_wxlhi)[i] = *(uint2*)h;
    ((uint2*)g_wxllo)[i] = *(uint2*)l;
}

// ---------------------------------------------------------------------------
extern "C" void kernel_launch(void* const* d_in, const int* in_sizes, int n_in,
                              void* d_out, int out_size)
{
    (void)in_sizes; (void)n_in; (void)out_size;

    const float* xt   = (const float*)d_in[0];
    const float* ctf  = (const float*)d_in[1];
    const float* W_x  = (const float*)d_in[2];
    const float* W_f  = (const float*)d_in[3];
    const float* b_f  = (const float*)d_in[4];
    const float* W_r  = (const float*)d_in[5];
    const float* b_r  = (const float*)d_in[6];
    const float* W_cx = (const float*)d_in[7];
    const float* b_cx = (const float*)d_in[8];
    const float* W_xl = (const float*)d_in[9];
    const float* b_xl = (const float*)d_in[10];
    float* out = (float*)d_out;

    float *Y, *bias;
    __half *xhi, *xlo, *h1hi, *h1lo, *hchi, *hclo, *whi, *wlo, *wxlhi, *wxllo;
    cudaGetSymbolAddress((void**)&Y,     g_Y);
    cudaGetSymbolAddress((void**)&bias,  g_bias);
    cudaGetSymbolAddress((void**)&xhi,   g_xhi);
    cudaGetSymbolAddress((void**)&xlo,   g_xlo);
    cudaGetSymbolAddress((void**)&h1hi,  g_h1hi);
    cudaGetSymbolAddress((void**)&h1lo,  g_h1lo);
    cudaGetSymbolAddress((void**)&hchi,  g_hchi);
    cudaGetSymbolAddress((void**)&hclo,  g_hclo);
    cudaGetSymbolAddress((void**)&whi,   g_whi);
    cudaGetSymbolAddress((void**)&wlo,   g_wlo);
    cudaGetSymbolAddress((void**)&wxlhi, g_wxlhi);
    cudaGetSymbolAddress((void**)&wxllo, g_wxllo);

    cudaFuncSetAttribute(gemm_tc<0>, cudaFuncAttributeMaxDynamicSharedMemorySize,
                         GEMM_SMEM);
    cudaFuncSetAttribute(gemm_tc<1>, cudaFuncAttributeMaxDynamicSharedMemorySize,
                         GEMM_SMEM);

    pack_w<<<2048, 256>>>(W_x, W_f, W_r, W_cx, b_f, b_r, b_cx);
    pack_wxl<<<512, 256>>>(W_xl);
    split_f32<<<16384, 256>>>((const float4*)xt, (uint2*)xhi, (uint2*)xlo,
                              M_TOT * NIN / 4);

    // layer 0: fused 4-projection GEMM (N=2048) + scan
    gemm_tc<0><<<dim3(8, 128), 512, GEMM_SMEM>>>(xhi, xlo, whi, wlo, bias,
                                                 Y, nullptr, nullptr, NIN, NBIG);
    sru_scan<1><<<128, 128>>>(Y, ctf, nullptr, h1hi, h1lo, nullptr);

    // convert_x_layer: hconv = h1 @ W_xl^T + b_xl (fp16 hi/lo out)
    gemm_tc<1><<<dim3(4, 128), 512, GEMM_SMEM>>>(h1hi, h1lo, wxlhi, wxllo, b_xl,
                                                 nullptr, hchi, hclo, NOUT, NIN);

    // layer 1: fused 4-projection GEMM + scan
    gemm_tc<0><<<dim3(8, 128), 512, GEMM_SMEM>>>(hchi, hclo, whi, wlo, bias,
                                                 Y, nullptr, nullptr, NIN, NBIG);
    sru_scan<0><<<128, 128>>>(Y, ctf + E_TOT, out, nullptr, nullptr,
                              out + (size_t)M_TOT * NOUT);
}

// round 9
// speedup vs baseline: 2.3116x; 1.1339x over previous
#include <cuda_runtime.h>
#include <cuda_fp16.h>
#include <math.h>
#include <stdint.h>

// ---------------------------------------------------------------------------
// SRU, 2 layers. Legacy mma.sync HMMA (base sm_103 target; no tcgen05).
// Split-fp16 3-term GEMM: Y = Ahi*Bhi + Ahi*Blo + Alo*Bhi  (rel ~1e-5)
// R9: fuse the 3 split terms per K-chunk — one fragment load feeds 3 MMA
//     passes (LDS/MMA 192B -> 128B), syncs 96 -> 32. Block 128x256,
//     16 warps (2m x 8n, warp 64x32), BK=32, 3-stage cp.async.
// ---------------------------------------------------------------------------

#define T_STEPS 512
#define BATCH   32
#define NIN     1024
#define NOUT    512
#define M_TOT   16384
#define NBIG    2048
#define E_TOT   16384

__device__ __align__(256) float  g_Y[(size_t)M_TOT * NBIG];
__device__ __align__(256) __half g_xhi[(size_t)M_TOT * NIN];
__device__ __align__(256) __half g_xlo[(size_t)M_TOT * NIN];
__device__ __align__(256) __half g_h1hi[(size_t)M_TOT * NOUT];
__device__ __align__(256) __half g_h1lo[(size_t)M_TOT * NOUT];
__device__ __align__(256) __half g_hchi[(size_t)M_TOT * NIN];
__device__ __align__(256) __half g_hclo[(size_t)M_TOT * NIN];
__device__ __align__(256) __half g_whi[(size_t)NBIG * NIN];
__device__ __align__(256) __half g_wlo[(size_t)NBIG * NIN];
__device__ __align__(256) __half g_wxlhi[(size_t)NIN * NOUT];
__device__ __align__(256) __half g_wxllo[(size_t)NIN * NOUT];
__device__ __align__(256) float  g_bias[NBIG];

// ---------------------------------------------------------------------------
__device__ __forceinline__ uint32_t smem_u32(const void* p) {
    uint32_t a;
    asm("{ .reg .u64 t; cvta.to.shared.u64 t, %1; cvt.u32.u64 %0, t; }"
        : "=r"(a) : "l"(p));
    return a;
}
__device__ __forceinline__ void cp16(uint32_t d, const void* s) {
    asm volatile("cp.async.cg.shared.global [%0], [%1], 16;"
                 :: "r"(d), "l"(s) : "memory");
}
__device__ __forceinline__ void cp_commit() {
    asm volatile("cp.async.commit_group;" ::: "memory");
}
__device__ __forceinline__ void cp_wait1() {
    asm volatile("cp.async.wait_group 1;" ::: "memory");
}
__device__ __forceinline__ void ldsm4(uint32_t* r, uint32_t a) {
    asm volatile("ldmatrix.sync.aligned.m8n8.x4.shared.b16 {%0,%1,%2,%3}, [%4];"
                 : "=r"(r[0]), "=r"(r[1]), "=r"(r[2]), "=r"(r[3]) : "r"(a));
}
__device__ __forceinline__ void mma16816(float* c, const uint32_t* a,
                                         const uint32_t* b) {
    asm volatile(
        "mma.sync.aligned.m16n8k16.row.col.f32.f16.f16.f32 "
        "{%0,%1,%2,%3}, {%4,%5,%6,%7}, {%8,%9}, {%0,%1,%2,%3};"
        : "+f"(c[0]), "+f"(c[1]), "+f"(c[2]), "+f"(c[3])
        : "r"(a[0]), "r"(a[1]), "r"(a[2]), "r"(a[3]), "r"(b[0]), "r"(b[1]));
}

// ---------------------------------------------------------------------------
// GEMM: Y[M,N] = Ahi*Bhi^T + Ahi*Blo^T + Alo*Bhi^T   (all K-major)
// Per stage (BK=32): smem holds Ahi|Alo|Bhi|Blo slabs; fragments of Ahi/Bhi
// are loaded once and reused across the 3 passes.
// MODE 0: fp32 out + g_bias + sigmoid on n in [512,1536)
// MODE 1: fp16 hi/lo out + fp32 bias vector
// ---------------------------------------------------------------------------
#define ROWB        80
#define A_TILE      (128 * ROWB)            // 10240
#define B_TILE      (256 * ROWB)            // 20480
#define STAGE_BYTES (2 * A_TILE + 2 * B_TILE) // 61440
#define GEMM_SMEM   (3 * STAGE_BYTES)       // 184320

template <int MODE>
__global__ __launch_bounds__(512, 1)
void gemm_tc(const __half* __restrict__ Ahi, const __half* __restrict__ Alo,
             const __half* __restrict__ Bhi, const __half* __restrict__ Blo,
             const float* __restrict__ bias,
             float* __restrict__ Yf,
             __half* __restrict__ Yhi, __half* __restrict__ Ylo,
             int K, int ldy)
{
    extern __shared__ __align__(128) char smem_dyn[];
    const uint32_t sb0 = smem_u32(smem_dyn);

    const int tid  = threadIdx.x;
    const int lane = tid & 31;
    const int wid  = tid >> 5;               // 0..15
    const int m_warp = (wid >> 3) * 64;      // 0,64
    const int n_warp = (wid & 7) * 32;       // 0..224
    const int mb = blockIdx.y * 128;
    const int nb = blockIdx.x * 256;

    // ldmatrix lane addressing
    const int a_row  = m_warp + (lane & 15);
    const int a_coff = (lane >> 4) * 16;
    const int b_t    = lane >> 3;
    const int b_row  = n_warp + (b_t >> 1) * 8 + (lane & 7);
    const int b_coff = (b_t & 1) * 16;

    float acc[4][4][4];
    #pragma unroll
    for (int i = 0; i < 4; i++)
        #pragma unroll
        for (int j = 0; j < 4; j++)
            #pragma unroll
            for (int q = 0; q < 4; q++) acc[i][j][q] = 0.f;

    // per-thread cp.async mapping (3072 chunks of 16B / 512 threads = 6)
    const int r_a = tid >> 2, c_a = tid & 3;                 // A tiles
    const int r_b0 = tid >> 2, c_b0 = tid & 3;               // B first half
    const int r_b1 = (tid + 512) >> 2, c_b1 = tid & 3;       // B second half

    auto issue = [&](int buf, int k0) {
        const uint32_t st  = sb0 + buf * STAGE_BYTES;
        const uint32_t sAh = st;
        const uint32_t sAl = st + A_TILE;
        const uint32_t sBh = st + 2 * A_TILE;
        const uint32_t sBl = st + 2 * A_TILE + B_TILE;
        const __half* Agh = Ahi + (size_t)mb * K + k0;
        const __half* Agl = Alo + (size_t)mb * K + k0;
        const __half* Bgh = Bhi + (size_t)nb * K + k0;
        const __half* Bgl = Blo + (size_t)nb * K + k0;
        cp16(sAh + r_a * ROWB + c_a * 16,  Agh + (size_t)r_a * K + c_a * 8);
        cp16(sAl + r_a * ROWB + c_a * 16,  Agl + (size_t)r_a * K + c_a * 8);
        cp16(sBh + r_b0 * ROWB + c_b0 * 16, Bgh + (size_t)r_b0 * K + c_b0 * 8);
        cp16(sBh + r_b1 * ROWB + c_b1 * 16, Bgh + (size_t)r_b1 * K + c_b1 * 8);
        cp16(sBl + r_b0 * ROWB + c_b0 * 16, Bgl + (size_t)r_b0 * K + c_b0 * 8);
        cp16(sBl + r_b1 * ROWB + c_b1 * 16, Bgl + (size_t)r_b1 * K + c_b1 * 8);
    };

    const int nst = K >> 5;
    issue(0, 0);  cp_commit();
    issue(1, 32); cp_commit();

    int k_issue = 64, buf_issue = 2;
    int buf = 0;
    for (int s = 0; s < nst; s++) {
        cp_wait1();
        __syncthreads();
        if (k_issue < K) {
            issue(buf_issue, k_issue);
            k_issue += 32;
            buf_issue = (buf_issue == 2) ? 0 : buf_issue + 1;
        }
        cp_commit();

        const uint32_t st  = sb0 + buf * STAGE_BYTES;
        const uint32_t sAh = st;
        const uint32_t sAl = st + A_TILE;
        const uint32_t sBh = st + 2 * A_TILE;
        const uint32_t sBl = st + 2 * A_TILE + B_TILE;

        #pragma unroll
        for (int kk = 0; kk < 2; kk++) {
            uint32_t ah[4][4], al[4][4], bh[2][4], bl[2][4];
            // pass-1 + pass-2 fragments
            #pragma unroll
            for (int ma = 0; ma < 4; ma++)
                ldsm4(ah[ma], sAh + (uint32_t)(a_row + ma * 16) * ROWB
                              + kk * 32 + a_coff);
            #pragma unroll
            for (int n2 = 0; n2 < 2; n2++)
                ldsm4(bh[n2], sBh + (uint32_t)(b_row + n2 * 16) * ROWB
                              + kk * 32 + b_coff);
            #pragma unroll
            for (int n2 = 0; n2 < 2; n2++)
                ldsm4(bl[n2], sBl + (uint32_t)(b_row + n2 * 16) * ROWB
                              + kk * 32 + b_coff);
            // pass 1: Ahi * Bhi
            #pragma unroll
            for (int ma = 0; ma < 4; ma++)
                #pragma unroll
                for (int na = 0; na < 4; na++)
                    mma16816(acc[ma][na], ah[ma], &bh[na >> 1][(na & 1) * 2]);
            // load Alo under pass-2 cover
            #pragma unroll
            for (int ma = 0; ma < 4; ma++)
                ldsm4(al[ma], sAl + (uint32_t)(a_row + ma * 16) * ROWB
                              + kk * 32 + a_coff);
            // pass 2: Ahi * Blo
            #pragma unroll
            for (int ma = 0; ma < 4; ma++)
                #pragma unroll
                for (int na = 0; na < 4; na++)
                    mma16816(acc[ma][na], ah[ma], &bl[na >> 1][(na & 1) * 2]);
            // pass 3: Alo * Bhi
            #pragma unroll
            for (int ma = 0; ma < 4; ma++)
                #pragma unroll
                for (int na = 0; na < 4; na++)
                    mma16816(acc[ma][na], al[ma], &bh[na >> 1][(na & 1) * 2]);
        }
        buf = (buf == 2) ? 0 : buf + 1;
    }

    // ---- epilogue ----
    const int g  = lane >> 2;
    const int tg = lane & 3;
    #pragma unroll
    for (int ma = 0; ma < 4; ma++) {
        #pragma unroll
        for (int na = 0; na < 4; na++) {
            const int m = mb + m_warp + ma * 16 + g;
            const int n = nb + n_warp + na * 8 + tg * 2;
            const float2 bv = *(const float2*)&bias[n];
            float y0 = acc[ma][na][0] + bv.x;
            float y1 = acc[ma][na][1] + bv.y;
            float y2 = acc[ma][na][2] + bv.x;
            float y3 = acc[ma][na][3] + bv.y;
            if (MODE == 0) {
                if (n >= 512 && n < 1536) {
                    y0 = 1.f / (1.f + __expf(-y0));
                    y1 = 1.f / (1.f + __expf(-y1));
                    y2 = 1.f / (1.f + __expf(-y2));
                    y3 = 1.f / (1.f + __expf(-y3));
                }
                *(float2*)&Yf[(size_t)m * ldy + n]       = make_float2(y0, y1);
                *(float2*)&Yf[(size_t)(m + 8) * ldy + n] = make_float2(y2, y3);
            } else {
                __half h0 = __float2half_rn(y0), h1 = __float2half_rn(y1);
                __half h2 = __float2half_rn(y2), h3 = __float2half_rn(y3);
                __half l0 = __float2half_rn(y0 - __half2float(h0));
                __half l1 = __float2half_rn(y1 - __half2float(h1));
                __half l2 = __float2half_rn(y2 - __half2float(h2));
                __half l3 = __float2half_rn(y3 - __half2float(h3));
                *(__half2*)&Yhi[(size_t)m * ldy + n]       = __halves2half2(h0, h1);
                *(__half2*)&Yhi[(size_t)(m + 8) * ldy + n] = __halves2half2(h2, h3);
                *(__half2*)&Ylo[(size_t)m * ldy + n]       = __halves2half2(l0, l1);
                *(__half2*)&Ylo[(size_t)(m + 8) * ldy + n] = __halves2half2(l2, l3);
            }
        }
    }
}

// ---------------------------------------------------------------------------
// Scan: one thread per (b,o). Y layout [M,2048] = x|f|r|cx (f/r sigmoided).
// ---------------------------------------------------------------------------
template <int SPLIT>
__global__ __launch_bounds__(128)
void sru_scan(const float* __restrict__ Y, const float* __restrict__ c0,
              float* __restrict__ hf,
              __half* __restrict__ hhi, __half* __restrict__ hlo,
              float* __restrict__ cout)
{
    const int e = blockIdx.x * 128 + threadIdx.x;
    const int b = e >> 9, o = e & 511;
    float c = c0[e];
    #pragma unroll 2
    for (int t = 0; t < T_STEPS; t++) {
        const int m = t * BATCH + b;
        const size_t base = (size_t)m * NBIG;
        float x  = Y[base + o];
        float f  = Y[base + 512 + o];
        float r  = Y[base + 1024 + o];
        float cx = Y[base + 1536 + o];
        c = fmaf(f, c - x, x);
        float h = fmaf(r, tanhf(c) - cx, cx);
        const size_t oi = (size_t)m * NOUT + o;
        if (SPLIT) {
            __half hh = __float2half_rn(h);
            hhi[oi] = hh;
            hlo[oi] = __float2half_rn(h - __half2float(hh));
        } else {
            hf[oi] = h;
        }
    }
    if (!SPLIT) cout[e] = c;
}

// ---------------------------------------------------------------------------
__global__ __launch_bounds__(256)
void split_f32(const float4* __restrict__ src, uint2* __restrict__ hi,
               uint2* __restrict__ lo, int n4)
{
    const int i = blockIdx.x * 256 + threadIdx.x;
    if (i >= n4) return;
    float4 v = src[i];
    float a[4] = { v.x, v.y, v.z, v.w };
    __align__(8) __half h[4], l[4];
    #pragma unroll
    for (int j = 0; j < 4; j++) {
        h[j] = __float2half_rn(a[j]);
        l[j] = __float2half_rn(a[j] - __half2float(h[j]));
    }
    hi[i] = *(uint2*)h;
    lo[i] = *(uint2*)l;
}

__global__ __launch_bounds__(256)
void pack_w(const float* __restrict__ Wx, const float* __restrict__ Wf,
            const float* __restrict__ Wr, const float* __restrict__ Wcx,
            const float* __restrict__ bf, const float* __restrict__ br,
            const float* __restrict__ bcx)
{
    const int i = blockIdx.x * 256 + threadIdx.x;   // float4 idx, 524288 total
    const int n = i * 4;
    const int row = n >> 10, col = n & 1023;
    const int sel = row >> 9, lr = row & 511;
    const float* src = sel == 0 ? Wx : sel == 1 ? Wf : sel == 2 ? Wr : Wcx;
    float4 v = *(const float4*)(src + (size_t)lr * 1024 + col);
    float a[4] = { v.x, v.y, v.z, v.w };
    __align__(8) __half h[4], l[4];
    #pragma unroll
    for (int j = 0; j < 4; j++) {
        h[j] = __float2half_rn(a[j]);
        l[j] = __float2half_rn(a[j] - __half2float(h[j]));
    }
    ((uint2*)g_whi)[i] = *(uint2*)h;
    ((uint2*)g_wlo)[i] = *(uint2*)l;

    if (i < 512) {
        const int nb_ = i * 4;
        const int s2 = nb_ >> 9, off = nb_ & 511;
        float4 bv = make_float4(0.f, 0.f, 0.f, 0.f);
        if (s2 > 0) {
            const float* bs = s2 == 1 ? bf : s2 == 2 ? br : bcx;
            bv = *(const float4*)(bs + off);
        }
        *(float4*)(g_bias + nb_) = bv;
    }
}

__global__ __launch_bounds__(256)
void pack_wxl(const float* __restrict__ Wxl)
{
    const int i = blockIdx.x * 256 + threadIdx.x;   // 131072 float4s
    float4 v = *(const float4*)(Wxl + (size_t)i * 4);
    float a[4] = { v.x, v.y, v.z, v.w };
    __align__(8) __half h[4], l[4];
    #pragma unroll
    for (int j = 0; j < 4; j++) {
        h[j] = __float2half_rn(a[j]);
        l[j] = __float2half_rn(a[j] - __half2float(h[j]));
    }
    ((uint2*)g_wxlhi)[i] = *(uint2*)h;
    ((uint2*)g_wxllo)[i] = *(uint2*)l;
}

// ---------------------------------------------------------------------------
extern "C" void kernel_launch(void* const* d_in, const int* in_sizes, int n_in,
                              void* d_out, int out_size)
{
    (void)in_sizes; (void)n_in; (void)out_size;

    const float* xt   = (const float*)d_in[0];
    const float* ctf  = (const float*)d_in[1];
    const float* W_x  = (const float*)d_in[2];
    const float* W_f  = (const float*)d_in[3];
    const float* b_f  = (const float*)d_in[4];
    const float* W_r  = (const float*)d_in[5];
    const float* b_r  = (const float*)d_in[6];
    const float* W_cx = (const float*)d_in[7];
    const float* b_cx = (const float*)d_in[8];
    const float* W_xl = (const float*)d_in[9];
    const float* b_xl = (const float*)d_in[10];
    float* out = (float*)d_out;

    float *Y, *bias;
    __half *xhi, *xlo, *h1hi, *h1lo, *hchi, *hclo, *whi, *wlo, *wxlhi, *wxllo;
    cudaGetSymbolAddress((void**)&Y,     g_Y);
    cudaGetSymbolAddress((void**)&bias,  g_bias);
    cudaGetSymbolAddress((void**)&xhi,   g_xhi);
    cudaGetSymbolAddress((void**)&xlo,   g_xlo);
    cudaGetSymbolAddress((void**)&h1hi,  g_h1hi);
    cudaGetSymbolAddress((void**)&h1lo,  g_h1lo);
    cudaGetSymbolAddress((void**)&hchi,  g_hchi);
    cudaGetSymbolAddress((void**)&hclo,  g_hclo);
    cudaGetSymbolAddress((void**)&whi,   g_whi);
    cudaGetSymbolAddress((void**)&wlo,   g_wlo);
    cudaGetSymbolAddress((void**)&wxlhi, g_wxlhi);
    cudaGetSymbolAddress((void**)&wxllo, g_wxllo);

    cudaFuncSetAttribute(gemm_tc<0>, cudaFuncAttributeMaxDynamicSharedMemorySize,
                         GEMM_SMEM);
    cudaFuncSetAttribute(gemm_tc<1>, cudaFuncAttributeMaxDynamicSharedMemorySize,
                         GEMM_SMEM);

    pack_w<<<2048, 256>>>(W_x, W_f, W_r, W_cx, b_f, b_r, b_cx);
    pack_wxl<<<512, 256>>>(W_xl);
    split_f32<<<16384, 256>>>((const float4*)xt, (uint2*)xhi, (uint2*)xlo,
                              M_TOT * NIN / 4);

    // layer 0: fused 4-projection GEMM (N=2048) + scan
    gemm_tc<0><<<dim3(8, 128), 512, GEMM_SMEM>>>(xhi, xlo, whi, wlo, bias,
                                                 Y, nullptr, nullptr, NIN, NBIG);
    sru_scan<1><<<128, 128>>>(Y, ctf, nullptr, h1hi, h1lo, nullptr);

    // convert_x_layer: hconv = h1 @ W_xl^T + b_xl (fp16 hi/lo out)
    gemm_tc<1><<<dim3(4, 128), 512, GEMM_SMEM>>>(h1hi, h1lo, wxlhi, wxllo, b_xl,
                                                 nullptr, hchi, hclo, NOUT, NIN);

    // layer 1: fused 4-projection GEMM + scan
    gemm_tc<0><<<dim3(8, 128), 512, GEMM_SMEM>>>(hchi, hclo, whi, wlo, bias,
                                                 Y, nullptr, nullptr, NIN, NBIG);
    sru_scan<0><<<128, 128>>>(Y, ctf + E_TOT, out, nullptr, nullptr,
                              out + (size_t)M_TOT * NOUT);
}

// round 10
// speedup vs baseline: 2.3503x; 1.0168x over previous
#include <cuda_runtime.h>
#include <cuda_fp16.h>
#include <math.h>
#include <stdint.h>

// ---------------------------------------------------------------------------
// SRU, 2 layers. Legacy mma.sync HMMA (base sm_103 target; no tcgen05).
// Split-fp16 3-term GEMM: Y = Ahi*Bhi + Ahi*Blo + Alo*Bhi  (rel ~1e-5)
// R10: 128x128 block / 256 thr / 2-stage (41KB/stage, 82KB total) so TWO CTAs
//      co-reside per SM — cross-CTA overlap hides barriers, cp waits, epilogue.
// ---------------------------------------------------------------------------

#define T_STEPS 512
#define BATCH   32
#define NIN     1024
#define NOUT    512
#define M_TOT   16384
#define NBIG    2048
#define E_TOT   16384

__device__ __align__(256) float  g_Y[(size_t)M_TOT * NBIG];
__device__ __align__(256) __half g_xhi[(size_t)M_TOT * NIN];
__device__ __align__(256) __half g_xlo[(size_t)M_TOT * NIN];
__device__ __align__(256) __half g_h1hi[(size_t)M_TOT * NOUT];
__device__ __align__(256) __half g_h1lo[(size_t)M_TOT * NOUT];
__device__ __align__(256) __half g_hchi[(size_t)M_TOT * NIN];
__device__ __align__(256) __half g_hclo[(size_t)M_TOT * NIN];
__device__ __align__(256) __half g_whi[(size_t)NBIG * NIN];
__device__ __align__(256) __half g_wlo[(size_t)NBIG * NIN];
__device__ __align__(256) __half g_wxlhi[(size_t)NIN * NOUT];
__device__ __align__(256) __half g_wxllo[(size_t)NIN * NOUT];
__device__ __align__(256) float  g_bias[NBIG];

// ---------------------------------------------------------------------------
__device__ __forceinline__ uint32_t smem_u32(const void* p) {
    uint32_t a;
    asm("{ .reg .u64 t; cvta.to.shared.u64 t, %1; cvt.u32.u64 %0, t; }"
        : "=r"(a) : "l"(p));
    return a;
}
__device__ __forceinline__ void cp16(uint32_t d, const void* s) {
    asm volatile("cp.async.cg.shared.global [%0], [%1], 16;"
                 :: "r"(d), "l"(s) : "memory");
}
__device__ __forceinline__ void cp_commit() {
    asm volatile("cp.async.commit_group;" ::: "memory");
}
__device__ __forceinline__ void cp_wait1() {
    asm volatile("cp.async.wait_group 1;" ::: "memory");
}
__device__ __forceinline__ void ldsm4(uint32_t* r, uint32_t a) {
    asm volatile("ldmatrix.sync.aligned.m8n8.x4.shared.b16 {%0,%1,%2,%3}, [%4];"
                 : "=r"(r[0]), "=r"(r[1]), "=r"(r[2]), "=r"(r[3]) : "r"(a));
}
__device__ __forceinline__ void mma16816(float* c, const uint32_t* a,
                                         const uint32_t* b) {
    asm volatile(
        "mma.sync.aligned.m16n8k16.row.col.f32.f16.f16.f32 "
        "{%0,%1,%2,%3}, {%4,%5,%6,%7}, {%8,%9}, {%0,%1,%2,%3};"
        : "+f"(c[0]), "+f"(c[1]), "+f"(c[2]), "+f"(c[3])
        : "r"(a[0]), "r"(a[1]), "r"(a[2]), "r"(a[3]), "r"(b[0]), "r"(b[1]));
}

// ---------------------------------------------------------------------------
// GEMM: Y[M,N] = Ahi*Bhi^T + Ahi*Blo^T + Alo*Bhi^T   (all K-major)
// BM=128 BN=128 BK=32, 256 threads (8 warps: 2m x 4n, warp 64x32),
// 2-stage cp.async, 2 CTAs/SM. Smem rows 80B (conflict-free ldmatrix).
// MODE 0: fp32 out + g_bias + sigmoid on n in [512,1536)
// MODE 1: fp16 hi/lo out + fp32 bias vector
// ---------------------------------------------------------------------------
#define ROWB        80
#define SLAB        (128 * ROWB)            // 10240 B  (one 128x32-half tile)
#define STAGE_BYTES (4 * SLAB)              // 40960 B  (Ahi|Alo|Bhi|Blo)
#define GEMM_SMEM   (2 * STAGE_BYTES)       // 81920 B  -> 2 CTAs/SM

template <int MODE>
__global__ __launch_bounds__(256, 2)
void gemm_tc(const __half* __restrict__ Ahi, const __half* __restrict__ Alo,
             const __half* __restrict__ Bhi, const __half* __restrict__ Blo,
             const float* __restrict__ bias,
             float* __restrict__ Yf,
             __half* __restrict__ Yhi, __half* __restrict__ Ylo,
             int K, int ldy)
{
    extern __shared__ __align__(128) char smem_dyn[];
    const uint32_t sb0 = smem_u32(smem_dyn);

    const int tid  = threadIdx.x;
    const int lane = tid & 31;
    const int wid  = tid >> 5;               // 0..7
    const int m_warp = (wid >> 2) * 64;      // 0,64
    const int n_warp = (wid & 3) * 32;       // 0..96
    const int mb = blockIdx.y * 128;
    const int nb = blockIdx.x * 128;

    // ldmatrix lane addressing
    const int a_row  = m_warp + (lane & 15);
    const int a_coff = (lane >> 4) * 16;
    const int b_t    = lane >> 3;
    const int b_row  = n_warp + (b_t >> 1) * 8 + (lane & 7);
    const int b_coff = (b_t & 1) * 16;

    float acc[4][4][4];
    #pragma unroll
    for (int i = 0; i < 4; i++)
        #pragma unroll
        for (int j = 0; j < 4; j++)
            #pragma unroll
            for (int q = 0; q < 4; q++) acc[i][j][q] = 0.f;

    // cp.async mapping: per slab 512 16B chunks (128 rows x 4), 2 per thread.
    const int ld_col = tid & 3;               // 0..3 (x8 halves)
    const int ld_r0  = tid >> 2;              // 0..63
    // rows ld_r0 and ld_r0+64

    const __half* gsrc[4];
    gsrc[0] = Ahi + (size_t)mb * K;
    gsrc[1] = Alo + (size_t)mb * K;
    gsrc[2] = Bhi + (size_t)nb * K;
    gsrc[3] = Blo + (size_t)nb * K;

    auto issue = [&](int buf, int k0) {
        const uint32_t st = sb0 + buf * STAGE_BYTES;
        #pragma unroll
        for (int sl = 0; sl < 4; sl++) {
            const __half* g = gsrc[sl] + k0;
            const uint32_t sd = st + sl * SLAB;
            cp16(sd + ld_r0 * ROWB + ld_col * 16,
                 g + (size_t)ld_r0 * K + ld_col * 8);
            cp16(sd + (ld_r0 + 64) * ROWB + ld_col * 16,
                 g + (size_t)(ld_r0 + 64) * K + ld_col * 8);
        }
    };

    const int nst = K >> 5;
    issue(0, 0);  cp_commit();
    issue(1, 32); cp_commit();

    for (int s = 0; s < nst; s++) {
        cp_wait1();            // stage s complete
        __syncthreads();       // visible to all warps

        const uint32_t st  = sb0 + (s & 1) * STAGE_BYTES;
        const uint32_t sAh = st;
        const uint32_t sAl = st + SLAB;
        const uint32_t sBh = st + 2 * SLAB;
        const uint32_t sBl = st + 3 * SLAB;

        #pragma unroll
        for (int kk = 0; kk < 2; kk++) {
            uint32_t ah[4][4], al[4][4], bh[2][4], bl[2][4];
            #pragma unroll
            for (int ma = 0; ma < 4; ma++)
                ldsm4(ah[ma], sAh + (uint32_t)(a_row + ma * 16) * ROWB
                              + kk * 32 + a_coff);
            #pragma unroll
            for (int n2 = 0; n2 < 2; n2++)
                ldsm4(bh[n2], sBh + (uint32_t)(b_row + n2 * 16) * ROWB
                              + kk * 32 + b_coff);
            #pragma unroll
            for (int n2 = 0; n2 < 2; n2++)
                ldsm4(bl[n2], sBl + (uint32_t)(b_row + n2 * 16) * ROWB
                              + kk * 32 + b_coff);
            // pass 1: Ahi * Bhi
            #pragma unroll
            for (int ma = 0; ma < 4; ma++)
                #pragma unroll
                for (int na = 0; na < 4; na++)
                    mma16816(acc[ma][na], ah[ma], &bh[na >> 1][(na & 1) * 2]);
            // load Alo under MMA cover
            #pragma unroll
            for (int ma = 0; ma < 4; ma++)
                ldsm4(al[ma], sAl + (uint32_t)(a_row + ma * 16) * ROWB
                              + kk * 32 + a_coff);
            // pass 2: Ahi * Blo
            #pragma unroll
            for (int ma = 0; ma < 4; ma++)
                #pragma unroll
                for (int na = 0; na < 4; na++)
                    mma16816(acc[ma][na], ah[ma], &bl[na >> 1][(na & 1) * 2]);
            // pass 3: Alo * Bhi
            #pragma unroll
            for (int ma = 0; ma < 4; ma++)
                #pragma unroll
                for (int na = 0; na < 4; na++)
                    mma16816(acc[ma][na], al[ma], &bh[na >> 1][(na & 1) * 2]);
        }

        __syncthreads();       // all warps done reading buf s&1
        const int k_next = (s + 2) * 32;
        if (k_next < K) issue(s & 1, k_next);
        cp_commit();
    }

    // ---- epilogue ----
    const int g  = lane >> 2;
    const int tg = lane & 3;
    #pragma unroll
    for (int ma = 0; ma < 4; ma++) {
        #pragma unroll
        for (int na = 0; na < 4; na++) {
            const int m = mb + m_warp + ma * 16 + g;
            const int n = nb + n_warp + na * 8 + tg * 2;
            const float2 bv = *(const float2*)&bias[n];
            float y0 = acc[ma][na][0] + bv.x;
            float y1 = acc[ma][na][1] + bv.y;
            float y2 = acc[ma][na][2] + bv.x;
            float y3 = acc[ma][na][3] + bv.y;
            if (MODE == 0) {
                if (n >= 512 && n < 1536) {
                    y0 = 1.f / (1.f + __expf(-y0));
                    y1 = 1.f / (1.f + __expf(-y1));
                    y2 = 1.f / (1.f + __expf(-y2));
                    y3 = 1.f / (1.f + __expf(-y3));
                }
                *(float2*)&Yf[(size_t)m * ldy + n]       = make_float2(y0, y1);
                *(float2*)&Yf[(size_t)(m + 8) * ldy + n] = make_float2(y2, y3);
            } else {
                __half h0 = __float2half_rn(y0), h1 = __float2half_rn(y1);
                __half h2 = __float2half_rn(y2), h3 = __float2half_rn(y3);
                __half l0 = __float2half_rn(y0 - __half2float(h0));
                __half l1 = __float2half_rn(y1 - __half2float(h1));
                __half l2 = __float2half_rn(y2 - __half2float(h2));
                __half l3 = __float2half_rn(y3 - __half2float(h3));
                *(__half2*)&Yhi[(size_t)m * ldy + n]       = __halves2half2(h0, h1);
                *(__half2*)&Yhi[(size_t)(m + 8) * ldy + n] = __halves2half2(h2, h3);
                *(__half2*)&Ylo[(size_t)m * ldy + n]       = __halves2half2(l0, l1);
                *(__half2*)&Ylo[(size_t)(m + 8) * ldy + n] = __halves2half2(l2, l3);
            }
        }
    }
}

// ---------------------------------------------------------------------------
// Scan: one thread per (b,o). Y layout [M,2048] = x|f|r|cx (f/r sigmoided).
// ---------------------------------------------------------------------------
template <int SPLIT>
__global__ __launch_bounds__(128)
void sru_scan(const float* __restrict__ Y, const float* __restrict__ c0,
              float* __restrict__ hf,
              __half* __restrict__ hhi, __half* __restrict__ hlo,
              float* __restrict__ cout)
{
    const int e = blockIdx.x * 128 + threadIdx.x;
    const int b = e >> 9, o = e & 511;
    float c = c0[e];
    #pragma unroll 2
    for (int t = 0; t < T_STEPS; t++) {
        const int m = t * BATCH + b;
        const size_t base = (size_t)m * NBIG;
        float x  = Y[base + o];
        float f  = Y[base + 512 + o];
        float r  = Y[base + 1024 + o];
        float cx = Y[base + 1536 + o];
        c = fmaf(f, c - x, x);
        float h = fmaf(r, tanhf(c) - cx, cx);
        const size_t oi = (size_t)m * NOUT + o;
        if (SPLIT) {
            __half hh = __float2half_rn(h);
            hhi[oi] = hh;
            hlo[oi] = __float2half_rn(h - __half2float(hh));
        } else {
            hf[oi] = h;
        }
    }
    if (!SPLIT) cout[e] = c;
}

// ---------------------------------------------------------------------------
__global__ __launch_bounds__(256)
void split_f32(const float4* __restrict__ src, uint2* __restrict__ hi,
               uint2* __restrict__ lo, int n4)
{
    const int i = blockIdx.x * 256 + threadIdx.x;
    if (i >= n4) return;
    float4 v = src[i];
    float a[4] = { v.x, v.y, v.z, v.w };
    __align__(8) __half h[4], l[4];
    #pragma unroll
    for (int j = 0; j < 4; j++) {
        h[j] = __float2half_rn(a[j]);
        l[j] = __float2half_rn(a[j] - __half2float(h[j]));
    }
    hi[i] = *(uint2*)h;
    lo[i] = *(uint2*)l;
}

__global__ __launch_bounds__(256)
void pack_w(const float* __restrict__ Wx, const float* __restrict__ Wf,
            const float* __restrict__ Wr, const float* __restrict__ Wcx,
            const float* __restrict__ bf, const float* __restrict__ br,
            const float* __restrict__ bcx)
{
    const int i = blockIdx.x * 256 + threadIdx.x;   // float4 idx, 524288 total
    const int n = i * 4;
    const int row = n >> 10, col = n & 1023;
    const int sel = row >> 9, lr = row & 511;
    const float* src = sel == 0 ? Wx : sel == 1 ? Wf : sel == 2 ? Wr : Wcx;
    float4 v = *(const float4*)(src + (size_t)lr * 1024 + col);
    float a[4] = { v.x, v.y, v.z, v.w };
    __align__(8) __half h[4], l[4];
    #pragma unroll
    for (int j = 0; j < 4; j++) {
        h[j] = __float2half_rn(a[j]);
        l[j] = __float2half_rn(a[j] - __half2float(h[j]));
    }
    ((uint2*)g_whi)[i] = *(uint2*)h;
    ((uint2*)g_wlo)[i] = *(uint2*)l;

    if (i < 512) {
        const int nb_ = i * 4;
        const int s2 = nb_ >> 9, off = nb_ & 511;
        float4 bv = make_float4(0.f, 0.f, 0.f, 0.f);
        if (s2 > 0) {
            const float* bs = s2 == 1 ? bf : s2 == 2 ? br : bcx;
            bv = *(const float4*)(bs + off);
        }
        *(float4*)(g_bias + nb_) = bv;
    }
}

__global__ __launch_bounds__(256)
void pack_wxl(const float* __restrict__ Wxl)
{
    const int i = blockIdx.x * 256 + threadIdx.x;   // 131072 float4s
    float4 v = *(const float4*)(Wxl + (size_t)i * 4);
    float a[4] = { v.x, v.y, v.z, v.w };
    __align__(8) __half h[4], l[4];
    #pragma unroll
    for (int j = 0; j < 4; j++) {
        h[j] = __float2half_rn(a[j]);
        l[j] = __float2half_rn(a[j] - __half2float(h[j]));
    }
    ((uint2*)g_wxlhi)[i] = *(uint2*)h;
    ((uint2*)g_wxllo)[i] = *(uint2*)l;
}

// ---------------------------------------------------------------------------
extern "C" void kernel_launch(void* const* d_in, const int* in_sizes, int n_in,
                              void* d_out, int out_size)
{
    (void)in_sizes; (void)n_in; (void)out_size;

    const float* xt   = (const float*)d_in[0];
    const float* ctf  = (const float*)d_in[1];
    const float* W_x  = (const float*)d_in[2];
    const float* W_f  = (const float*)d_in[3];
    const float* b_f  = (const float*)d_in[4];
    const float* W_r  = (const float*)d_in[5];
    const float* b_r  = (const float*)d_in[6];
    const float* W_cx = (const float*)d_in[7];
    const float* b_cx = (const float*)d_in[8];
    const float* W_xl = (const float*)d_in[9];
    const float* b_xl = (const float*)d_in[10];
    float* out = (float*)d_out;

    float *Y, *bias;
    __half *xhi, *xlo, *h1hi, *h1lo, *hchi, *hclo, *whi, *wlo, *wxlhi, *wxllo;
    cudaGetSymbolAddress((void**)&Y,     g_Y);
    cudaGetSymbolAddress((void**)&bias,  g_bias);
    cudaGetSymbolAddress((void**)&xhi,   g_xhi);
    cudaGetSymbolAddress((void**)&xlo,   g_xlo);
    cudaGetSymbolAddress((void**)&h1hi,  g_h1hi);
    cudaGetSymbolAddress((void**)&h1lo,  g_h1lo);
    cudaGetSymbolAddress((void**)&hchi,  g_hchi);
    cudaGetSymbolAddress((void**)&hclo,  g_hclo);
    cudaGetSymbolAddress((void**)&whi,   g_whi);
    cudaGetSymbolAddress((void**)&wlo,   g_wlo);
    cudaGetSymbolAddress((void**)&wxlhi, g_wxlhi);
    cudaGetSymbolAddress((void**)&wxllo, g_wxllo);

    cudaFuncSetAttribute(gemm_tc<0>, cudaFuncAttributeMaxDynamicSharedMemorySize,
                         GEMM_SMEM);
    cudaFuncSetAttribute(gemm_tc<1>, cudaFuncAttributeMaxDynamicSharedMemorySize,
                         GEMM_SMEM);

    pack_w<<<2048, 256>>>(W_x, W_f, W_r, W_cx, b_f, b_r, b_cx);
    pack_wxl<<<512, 256>>>(W_xl);
    split_f32<<<16384, 256>>>((const float4*)xt, (uint2*)xhi, (uint2*)xlo,
                              M_TOT * NIN / 4);

    // layer 0: fused 4-projection GEMM (N=2048) + scan
    gemm_tc<0><<<dim3(16, 128), 256, GEMM_SMEM>>>(xhi, xlo, whi, wlo, bias,
                                                  Y, nullptr, nullptr, NIN, NBIG);
    sru_scan<1><<<128, 128>>>(Y, ctf, nullptr, h1hi, h1lo, nullptr);

    // convert_x_layer: hconv = h1 @ W_xl^T + b_xl (fp16 hi/lo out)
    gemm_tc<1><<<dim3(8, 128), 256, GEMM_SMEM>>>(h1hi, h1lo, wxlhi, wxllo, b_xl,
                                                 nullptr, hchi, hclo, NOUT, NIN);

    // layer 1: fused 4-projection GEMM + scan
    gemm_tc<0><<<dim3(16, 128), 256, GEMM_SMEM>>>(hchi, hclo, whi, wlo, bias,
                                                  Y, nullptr, nullptr, NIN, NBIG);
    sru_scan<0><<<128, 128>>>(Y, ctf + E_TOT, out, nullptr, nullptr,
                              out + (size_t)M_TOT * NOUT);
}

// round 11
// speedup vs baseline: 2.5236x; 1.0737x over previous
#include <cuda_runtime.h>
#include <cuda_fp16.h>
#include <math.h>
#include <stdint.h>

// ---------------------------------------------------------------------------
// SRU, 2 layers. Legacy mma.sync HMMA (base sm_103 target; no tcgen05).
// Split-fp16 3-term GEMM: Y = Ahi*Bhi + Ahi*Blo + Alo*Bhi  (rel ~1e-5)
// R11: GEMM -> BK=16, 4-stage cp.async, single sync/stage, cp issued right
//      after the barrier (memory overlaps all MMA), 2 CTAs/SM.
//      Scan  -> depth-4 software prefetch (~2.3 TB/s effective).
// ---------------------------------------------------------------------------

#define T_STEPS 512
#define BATCH   32
#define NIN     1024
#define NOUT    512
#define M_TOT   16384
#define NBIG    2048
#define E_TOT   16384

__device__ __align__(256) float  g_Y[(size_t)M_TOT * NBIG];
__device__ __align__(256) __half g_xhi[(size_t)M_TOT * NIN];
__device__ __align__(256) __half g_xlo[(size_t)M_TOT * NIN];
__device__ __align__(256) __half g_h1hi[(size_t)M_TOT * NOUT];
__device__ __align__(256) __half g_h1lo[(size_t)M_TOT * NOUT];
__device__ __align__(256) __half g_hchi[(size_t)M_TOT * NIN];
__device__ __align__(256) __half g_hclo[(size_t)M_TOT * NIN];
__device__ __align__(256) __half g_whi[(size_t)NBIG * NIN];
__device__ __align__(256) __half g_wlo[(size_t)NBIG * NIN];
__device__ __align__(256) __half g_wxlhi[(size_t)NIN * NOUT];
__device__ __align__(256) __half g_wxllo[(size_t)NIN * NOUT];
__device__ __align__(256) float  g_bias[NBIG];

// ---------------------------------------------------------------------------
__device__ __forceinline__ uint32_t smem_u32(const void* p) {
    uint32_t a;
    asm("{ .reg .u64 t; cvta.to.shared.u64 t, %1; cvt.u32.u64 %0, t; }"
        : "=r"(a) : "l"(p));
    return a;
}
__device__ __forceinline__ void cp16(uint32_t d, const void* s) {
    asm volatile("cp.async.cg.shared.global [%0], [%1], 16;"
                 :: "r"(d), "l"(s) : "memory");
}
__device__ __forceinline__ void cp_commit() {
    asm volatile("cp.async.commit_group;" ::: "memory");
}
__device__ __forceinline__ void cp_wait2() {
    asm volatile("cp.async.wait_group 2;" ::: "memory");
}
__device__ __forceinline__ void ldsm4(uint32_t* r, uint32_t a) {
    asm volatile("ldmatrix.sync.aligned.m8n8.x4.shared.b16 {%0,%1,%2,%3}, [%4];"
                 : "=r"(r[0]), "=r"(r[1]), "=r"(r[2]), "=r"(r[3]) : "r"(a));
}
__device__ __forceinline__ void mma16816(float* c, const uint32_t* a,
                                         const uint32_t* b) {
    asm volatile(
        "mma.sync.aligned.m16n8k16.row.col.f32.f16.f16.f32 "
        "{%0,%1,%2,%3}, {%4,%5,%6,%7}, {%8,%9}, {%0,%1,%2,%3};"
        : "+f"(c[0]), "+f"(c[1]), "+f"(c[2]), "+f"(c[3])
        : "r"(a[0]), "r"(a[1]), "r"(a[2]), "r"(a[3]), "r"(b[0]), "r"(b[1]));
}

// ---------------------------------------------------------------------------
// GEMM: Y[M,N] = Ahi*Bhi^T + Ahi*Blo^T + Alo*Bhi^T   (all K-major)
// BM=128 BN=128 BK=16, 256 threads (8 warps: 2m x 4n, warp 64x32),
// 4-stage cp.async, single __syncthreads per stage, 2 CTAs/SM.
// Smem rows 48B (stride 3 x 16B, odd -> conflict-free ldmatrix).
// MODE 0: fp32 out + g_bias + sigmoid on n in [512,1536)
// MODE 1: fp16 hi/lo out + fp32 bias vector
// ---------------------------------------------------------------------------
#define ROWB        48
#define SLAB        (128 * ROWB)            // 6144 B  (one 128x16-half tile)
#define STAGE_BYTES (4 * SLAB)              // 24576 B (Ahi|Alo|Bhi|Blo)
#define GEMM_SMEM   (4 * STAGE_BYTES)       // 98304 B -> 2 CTAs/SM

template <int MODE>
__global__ __launch_bounds__(256, 2)
void gemm_tc(const __half* __restrict__ Ahi, const __half* __restrict__ Alo,
             const __half* __restrict__ Bhi, const __half* __restrict__ Blo,
             const float* __restrict__ bias,
             float* __restrict__ Yf,
             __half* __restrict__ Yhi, __half* __restrict__ Ylo,
             int K, int ldy)
{
    extern __shared__ __align__(128) char smem_dyn[];
    const uint32_t sb0 = smem_u32(smem_dyn);

    const int tid  = threadIdx.x;
    const int lane = tid & 31;
    const int wid  = tid >> 5;               // 0..7
    const int m_warp = (wid >> 2) * 64;      // 0,64
    const int n_warp = (wid & 3) * 32;       // 0..96
    const int mb = blockIdx.y * 128;
    const int nb = blockIdx.x * 128;

    // ldmatrix lane addressing (BK=16: one k16 slab, 32B rows)
    const int a_row  = m_warp + (lane & 15);
    const int a_coff = (lane >> 4) * 16;
    const int b_t    = lane >> 3;
    const int b_row  = n_warp + (b_t >> 1) * 8 + (lane & 7);
    const int b_coff = (b_t & 1) * 16;

    float acc[4][4][4];
    #pragma unroll
    for (int i = 0; i < 4; i++)
        #pragma unroll
        for (int j = 0; j < 4; j++)
            #pragma unroll
            for (int q = 0; q < 4; q++) acc[i][j][q] = 0.f;

    // cp.async: per slab 256 chunks of 16B (128 rows x 2); 1 chunk/thread/slab
    const int r_ld = tid >> 1;                // 0..127
    const int c_ld = tid & 1;                 // 0..1

    const __half* gsrc[4];
    gsrc[0] = Ahi + (size_t)mb * K;
    gsrc[1] = Alo + (size_t)mb * K;
    gsrc[2] = Bhi + (size_t)nb * K;
    gsrc[3] = Blo + (size_t)nb * K;

    auto issue = [&](int buf, int k0) {
        const uint32_t st = sb0 + buf * STAGE_BYTES;
        #pragma unroll
        for (int sl = 0; sl < 4; sl++) {
            cp16(st + sl * SLAB + r_ld * ROWB + c_ld * 16,
                 gsrc[sl] + k0 + (size_t)r_ld * K + c_ld * 8);
        }
    };

    const int nst = K >> 4;
    issue(0, 0);  cp_commit();
    issue(1, 16); cp_commit();
    issue(2, 32); cp_commit();

    for (int s = 0; s < nst; s++) {
        cp_wait2();            // stage s arrived (<=2 groups pending)
        __syncthreads();       // all warps done with buf (s-1)&3, data visible

        const int kn = (s + 3) << 4;
        if (kn < K) issue((s + 3) & 3, kn);   // overwrites buf (s-1)&3: safe
        cp_commit();                           // (empty group ok for counting)

        const uint32_t st  = sb0 + (s & 3) * STAGE_BYTES;
        const uint32_t sAh = st;
        const uint32_t sAl = st + SLAB;
        const uint32_t sBh = st + 2 * SLAB;
        const uint32_t sBl = st + 3 * SLAB;

        uint32_t ah[4][4], al[4][4], bh[2][4], bl[2][4];
        #pragma unroll
        for (int ma = 0; ma < 4; ma++)
            ldsm4(ah[ma], sAh + (uint32_t)(a_row + ma * 16) * ROWB + a_coff);
        #pragma unroll
        for (int n2 = 0; n2 < 2; n2++)
            ldsm4(bh[n2], sBh + (uint32_t)(b_row + n2 * 16) * ROWB + b_coff);
        #pragma unroll
        for (int n2 = 0; n2 < 2; n2++)
            ldsm4(bl[n2], sBl + (uint32_t)(b_row + n2 * 16) * ROWB + b_coff);
        // pass 1: Ahi * Bhi
        #pragma unroll
        for (int ma = 0; ma < 4; ma++)
            #pragma unroll
            for (int na = 0; na < 4; na++)
                mma16816(acc[ma][na], ah[ma], &bh[na >> 1][(na & 1) * 2]);
        // load Alo under MMA cover
        #pragma unroll
        for (int ma = 0; ma < 4; ma++)
            ldsm4(al[ma], sAl + (uint32_t)(a_row + ma * 16) * ROWB + a_coff);
        // pass 2: Ahi * Blo
        #pragma unroll
        for (int ma = 0; ma < 4; ma++)
            #pragma unroll
            for (int na = 0; na < 4; na++)
                mma16816(acc[ma][na], ah[ma], &bl[na >> 1][(na & 1) * 2]);
        // pass 3: Alo * Bhi
        #pragma unroll
        for (int ma = 0; ma < 4; ma++)
            #pragma unroll
            for (int na = 0; na < 4; na++)
                mma16816(acc[ma][na], al[ma], &bh[na >> 1][(na & 1) * 2]);
    }

    // ---- epilogue ----
    const int g  = lane >> 2;
    const int tg = lane & 3;
    #pragma unroll
    for (int ma = 0; ma < 4; ma++) {
        #pragma unroll
        for (int na = 0; na < 4; na++) {
            const int m = mb + m_warp + ma * 16 + g;
            const int n = nb + n_warp + na * 8 + tg * 2;
            const float2 bv = *(const float2*)&bias[n];
            float y0 = acc[ma][na][0] + bv.x;
            float y1 = acc[ma][na][1] + bv.y;
            float y2 = acc[ma][na][2] + bv.x;
            float y3 = acc[ma][na][3] + bv.y;
            if (MODE == 0) {
                if (n >= 512 && n < 1536) {
                    y0 = 1.f / (1.f + __expf(-y0));
                    y1 = 1.f / (1.f + __expf(-y1));
                    y2 = 1.f / (1.f + __expf(-y2));
                    y3 = 1.f / (1.f + __expf(-y3));
                }
                *(float2*)&Yf[(size_t)m * ldy + n]       = make_float2(y0, y1);
                *(float2*)&Yf[(size_t)(m + 8) * ldy + n] = make_float2(y2, y3);
            } else {
                __half h0 = __float2half_rn(y0), h1 = __float2half_rn(y1);
                __half h2 = __float2half_rn(y2), h3 = __float2half_rn(y3);
                __half l0 = __float2half_rn(y0 - __half2float(h0));
                __half l1 = __float2half_rn(y1 - __half2float(h1));
                __half l2 = __float2half_rn(y2 - __half2float(h2));
                __half l3 = __float2half_rn(y3 - __half2float(h3));
                *(__half2*)&Yhi[(size_t)m * ldy + n]       = __halves2half2(h0, h1);
                *(__half2*)&Yhi[(size_t)(m + 8) * ldy + n] = __halves2half2(h2, h3);
                *(__half2*)&Ylo[(size_t)m * ldy + n]       = __halves2half2(l0, l1);
                *(__half2*)&Ylo[(size_t)(m + 8) * ldy + n] = __halves2half2(l2, l3);
            }
        }
    }
}

// ---------------------------------------------------------------------------
// Scan: one thread per (b,o). Y layout [M,2048] = x|f|r|cx (f/r sigmoided).
// Depth-4 software prefetch: loads for t+4 issued while computing t.
// ---------------------------------------------------------------------------
template <int SPLIT>
__global__ __launch_bounds__(128)
void sru_scan(const float* __restrict__ Y, const float* __restrict__ c0,
              float* __restrict__ hf,
              __half* __restrict__ hhi, __half* __restrict__ hlo,
              float* __restrict__ cout)
{
    const int e = blockIdx.x * 128 + threadIdx.x;
    const int b = e >> 9, o = e & 511;
    float c = c0[e];

    const float* p = Y + (size_t)b * NBIG + o;
    const size_t STEP = (size_t)BATCH * NBIG;      // 65536 floats per t

    float X[4], F[4], R[4], CX[4];
    #pragma unroll
    for (int i = 0; i < 4; i++) {
        const float* q = p + (size_t)i * STEP;
        X[i] = q[0]; F[i] = q[512]; R[i] = q[1024]; CX[i] = q[1536];
    }

    for (int t = 0; t < T_STEPS; t += 4) {
        #pragma unroll
        for (int j = 0; j < 4; j++) {
            const float x  = X[j];
            const float f  = F[j];
            const float r  = R[j];
            const float cx = CX[j];
            const int tp = t + 4 + j;
            if (tp < T_STEPS) {      // prefetch t+4+j into slot j
                const float* q = p + (size_t)tp * STEP;
                X[j] = q[0]; F[j] = q[512]; R[j] = q[1024]; CX[j] = q[1536];
            }
            c = fmaf(f, c - x, x);
            const float h = fmaf(r, tanhf(c) - cx, cx);
            const size_t oi = (size_t)((t + j) * BATCH + b) * NOUT + o;
            if (SPLIT) {
                __half hh = __float2half_rn(h);
                hhi[oi] = hh;
                hlo[oi] = __float2half_rn(h - __half2float(hh));
            } else {
                hf[oi] = h;
            }
        }
    }
    if (!SPLIT) cout[e] = c;
}

// ---------------------------------------------------------------------------
__global__ __launch_bounds__(256)
void split_f32(const float4* __restrict__ src, uint2* __restrict__ hi,
               uint2* __restrict__ lo, int n4)
{
    const int i = blockIdx.x * 256 + threadIdx.x;
    if (i >= n4) return;
    float4 v = src[i];
    float a[4] = { v.x, v.y, v.z, v.w };
    __align__(8) __half h[4], l[4];
    #pragma unroll
    for (int j = 0; j < 4; j++) {
        h[j] = __float2half_rn(a[j]);
        l[j] = __float2half_rn(a[j] - __half2float(h[j]));
    }
    hi[i] = *(uint2*)h;
    lo[i] = *(uint2*)l;
}

__global__ __launch_bounds__(256)
void pack_w(const float* __restrict__ Wx, const float* __restrict__ Wf,
            const float* __restrict__ Wr, const float* __restrict__ Wcx,
            const float* __restrict__ bf, const float* __restrict__ br,
            const float* __restrict__ bcx)
{
    const int i = blockIdx.x * 256 + threadIdx.x;   // float4 idx, 524288 total
    const int n = i * 4;
    const int row = n >> 10, col = n & 1023;
    const int sel = row >> 9, lr = row & 511;
    const float* src = sel == 0 ? Wx : sel == 1 ? Wf : sel == 2 ? Wr : Wcx;
    float4 v = *(const float4*)(src + (size_t)lr * 1024 + col);
    float a[4] = { v.x, v.y, v.z, v.w };
    __align__(8) __half h[4], l[4];
    #pragma unroll
    for (int j = 0; j < 4; j++) {
        h[j] = __float2half_rn(a[j]);
        l[j] = __float2half_rn(a[j] - __half2float(h[j]));
    }
    ((uint2*)g_whi)[i] = *(uint2*)h;
    ((uint2*)g_wlo)[i] = *(uint2*)l;

    if (i < 512) {
        const int nb_ = i * 4;
        const int s2 = nb_ >> 9, off = nb_ & 511;
        float4 bv = make_float4(0.f, 0.f, 0.f, 0.f);
        if (s2 > 0) {
            const float* bs = s2 == 1 ? bf : s2 == 2 ? br : bcx;
            bv = *(const float4*)(bs + off);
        }
        *(float4*)(g_bias + nb_) = bv;
    }
}

__global__ __launch_bounds__(256)
void pack_wxl(const float* __restrict__ Wxl)
{
    const int i = blockIdx.x * 256 + threadIdx.x;   // 131072 float4s
    float4 v = *(const float4*)(Wxl + (size_t)i * 4);
    float a[4] = { v.x, v.y, v.z, v.w };
    __align__(8) __half h[4], l[4];
    #pragma unroll
    for (int j = 0; j < 4; j++) {
        h[j] = __float2half_rn(a[j]);
        l[j] = __float2half_rn(a[j] - __half2float(h[j]));
    }
    ((uint2*)g_wxlhi)[i] = *(uint2*)h;
    ((uint2*)g_wxllo)[i] = *(uint2*)l;
}

// ---------------------------------------------------------------------------
extern "C" void kernel_launch(void* const* d_in, const int* in_sizes, int n_in,
                              void* d_out, int out_size)
{
    (void)in_sizes; (void)n_in; (void)out_size;

    const float* xt   = (const float*)d_in[0];
    const float* ctf  = (const float*)d_in[1];
    const float* W_x  = (const float*)d_in[2];
    const float* W_f  = (const float*)d_in[3];
    const float* b_f  = (const float*)d_in[4];
    const float* W_r  = (const float*)d_in[5];
    const float* b_r  = (const float*)d_in[6];
    const float* W_cx = (const float*)d_in[7];
    const float* b_cx = (const float*)d_in[8];
    const float* W_xl = (const float*)d_in[9];
    const float* b_xl = (const float*)d_in[10];
    float* out = (float*)d_out;

    float *Y, *bias;
    __half *xhi, *xlo, *h1hi, *h1lo, *hchi, *hclo, *whi, *wlo, *wxlhi, *wxllo;
    cudaGetSymbolAddress((void**)&Y,     g_Y);
    cudaGetSymbolAddress((void**)&bias,  g_bias);
    cudaGetSymbolAddress((void**)&xhi,   g_xhi);
    cudaGetSymbolAddress((void**)&xlo,   g_xlo);
    cudaGetSymbolAddress((void**)&h1hi,  g_h1hi);
    cudaGetSymbolAddress((void**)&h1lo,  g_h1lo);
    cudaGetSymbolAddress((void**)&hchi,  g_hchi);
    cudaGetSymbolAddress((void**)&hclo,  g_hclo);
    cudaGetSymbolAddress((void**)&whi,   g_whi);
    cudaGetSymbolAddress((void**)&wlo,   g_wlo);
    cudaGetSymbolAddress((void**)&wxlhi, g_wxlhi);
    cudaGetSymbolAddress((void**)&wxllo, g_wxllo);

    cudaFuncSetAttribute(gemm_tc<0>, cudaFuncAttributeMaxDynamicSharedMemorySize,
                         GEMM_SMEM);
    cudaFuncSetAttribute(gemm_tc<1>, cudaFuncAttributeMaxDynamicSharedMemorySize,
                         GEMM_SMEM);

    pack_w<<<2048, 256>>>(W_x, W_f, W_r, W_cx, b_f, b_r, b_cx);
    pack_wxl<<<512, 256>>>(W_xl);
    split_f32<<<16384, 256>>>((const float4*)xt, (uint2*)xhi, (uint2*)xlo,
                              M_TOT * NIN / 4);

    // layer 0: fused 4-projection GEMM (N=2048) + scan
    gemm_tc<0><<<dim3(16, 128), 256, GEMM_SMEM>>>(xhi, xlo, whi, wlo, bias,
                                                  Y, nullptr, nullptr, NIN, NBIG);
    sru_scan<1><<<128, 128>>>(Y, ctf, nullptr, h1hi, h1lo, nullptr);

    // convert_x_layer: hconv = h1 @ W_xl^T + b_xl (fp16 hi/lo out)
    gemm_tc<1><<<dim3(8, 128), 256, GEMM_SMEM>>>(h1hi, h1lo, wxlhi, wxllo, b_xl,
                                                 nullptr, hchi, hclo, NOUT, NIN);

    // layer 1: fused 4-projection GEMM + scan
    gemm_tc<0><<<dim3(16, 128), 256, GEMM_SMEM>>>(hchi, hclo, whi, wlo, bias,
                                                  Y, nullptr, nullptr, NIN, NBIG);
    sru_scan<0><<<128, 128>>>(Y, ctf + E_TOT, out, nullptr, nullptr,
                              out + (size_t)M_TOT * NOUT);
}